// round 2
// baseline (speedup 1.0000x reference)
#include <cuda_runtime.h>
#include <math.h>

#define BB 16
#define SS_ 512
#define DD 1024
#define HH 16
#define LL 12
#define DKK 64
#define DFFN 4096
#define ROWS (BB*SS_)   // 8192

// ------------------------- scratch (static device memory) -------------------
__device__ float g_xn[ROWS * DD];     // LN output
__device__ float g_t [ROWS * DD];     // shared QKV projection t
__device__ float g_o [ROWS * DD];     // attention output
__device__ float g_h [ROWS * DFFN];   // FFN hidden

// ------------------------- embedding + positional encoding ------------------
__global__ void embed_kernel(const int* __restrict__ masked,
                             const float* __restrict__ tok,
                             const float* __restrict__ seg,
                             float* __restrict__ x) {
    int bs = blockIdx.x;                 // 0..8191
    int s  = bs & (SS_ - 1);
    int id = masked[bs];
    const float* tp = tok + (size_t)id * DD;
    const float* sp = seg + DD;          // seg_emb[1]
    int j = threadIdx.x * 4;             // 256 threads * 4 = 1024
    const float L = 0.0089944730328f;    // ln(10000)/1024
    float f0 = expf(-(float)j * L);
    float f1 = expf(-(float)(j + 2) * L);
    float a0 = (float)s * f0;
    float a1 = (float)s * f1;
    float4 tv = *(const float4*)(tp + j);
    float4 sv = *(const float4*)(sp + j);
    float4 r;
    r.x = tv.x + sinf(a0) + sv.x;
    r.y = tv.y + cosf(a0) + sv.y;
    r.z = tv.z + sinf(a1) + sv.z;
    r.w = tv.w + cosf(a1) + sv.w;
    *(float4*)(x + (size_t)bs * DD + j) = r;
}

// ------------------------- layernorm ---------------------------------------
__global__ void ln_kernel(const float* __restrict__ x,
                          const float* __restrict__ gamma,
                          const float* __restrict__ beta,
                          float* __restrict__ y) {
    int row = blockIdx.x;
    int tid = threadIdx.x;               // 256
    const float4* xp = (const float4*)(x + (size_t)row * DD);
    float4 v = xp[tid];
    float s = v.x + v.y + v.z + v.w;
    float q = v.x*v.x + v.y*v.y + v.z*v.z + v.w*v.w;
    #pragma unroll
    for (int o = 16; o > 0; o >>= 1) {
        s += __shfl_down_sync(0xffffffffu, s, o);
        q += __shfl_down_sync(0xffffffffu, q, o);
    }
    __shared__ float ss[8], qs[8];
    __shared__ float mu, rstd;
    int wid = tid >> 5, lane = tid & 31;
    if (lane == 0) { ss[wid] = s; qs[wid] = q; }
    __syncthreads();
    if (tid == 0) {
        float S = 0.f, Q = 0.f;
        #pragma unroll
        for (int i = 0; i < 8; i++) { S += ss[i]; Q += qs[i]; }
        float m = S * (1.0f / DD);
        mu = m;
        rstd = rsqrtf(Q * (1.0f / DD) - m * m + 1e-5f);
    }
    __syncthreads();
    int j = tid * 4;
    float4 g  = *(const float4*)(gamma + j);
    float4 bt = *(const float4*)(beta + j);
    float m = mu, r = rstd;
    float4 out;
    out.x = (v.x - m) * r * g.x + bt.x;
    out.y = (v.y - m) * r * g.y + bt.y;
    out.z = (v.z - m) * r * g.z + bt.z;
    out.w = (v.w - m) * r * g.w + bt.w;
    *(float4*)(y + (size_t)row * DD + j) = out;
}

// ------------------------- SGEMM: C = A[MxK] * B[KxN] (+bias, +res, gelu) ---
// EPI: 0 = bias only, 1 = bias + residual(C in-place), 2 = bias + exact GELU
template <int EPI>
__global__ __launch_bounds__(256, 2)
void gemm_kernel(const float* __restrict__ A, const float* __restrict__ B,
                 const float* __restrict__ bias, float* __restrict__ C,
                 int M, int N, int K) {
    __shared__ float As[8][128];
    __shared__ float Bs[8][128];
    const int t = threadIdx.x;
    const int tx = t & 15, ty = t >> 4;
    const int bm = blockIdx.y, bn = blockIdx.x;

    const int aRow = t >> 1, aCol = (t & 1) * 4;
    const int bRow = t >> 5, bCol = (t & 31) * 4;
    const float* Ag = A + (size_t)(bm * 128 + aRow) * K + aCol;
    const float* Bg = B + (size_t)bRow * N + bn * 128 + bCol;

    float acc[8][8];
    #pragma unroll
    for (int i = 0; i < 8; i++)
        #pragma unroll
        for (int j = 0; j < 8; j++) acc[i][j] = 0.f;

    for (int k0 = 0; k0 < K; k0 += 8) {
        float4 av = *(const float4*)(Ag + k0);
        float4 bv = *(const float4*)(Bg + (size_t)k0 * N);
        __syncthreads();
        As[aCol + 0][aRow] = av.x;
        As[aCol + 1][aRow] = av.y;
        As[aCol + 2][aRow] = av.z;
        As[aCol + 3][aRow] = av.w;
        *(float4*)&Bs[bRow][bCol] = bv;
        __syncthreads();
        #pragma unroll
        for (int kk = 0; kk < 8; kk++) {
            float a[8], b[8];
            *(float4*)&a[0] = *(const float4*)&As[kk][ty * 8];
            *(float4*)&a[4] = *(const float4*)&As[kk][ty * 8 + 4];
            *(float4*)&b[0] = *(const float4*)&Bs[kk][tx * 8];
            *(float4*)&b[4] = *(const float4*)&Bs[kk][tx * 8 + 4];
            #pragma unroll
            for (int i = 0; i < 8; i++)
                #pragma unroll
                for (int j = 0; j < 8; j++)
                    acc[i][j] += a[i] * b[j];
        }
    }

    const int row0 = bm * 128 + ty * 8;
    const int col0 = bn * 128 + tx * 8;
    #pragma unroll
    for (int i = 0; i < 8; i++) {
        float* cp = C + (size_t)(row0 + i) * N + col0;
        #pragma unroll
        for (int j = 0; j < 8; j++) {
            float v = acc[i][j] + bias[col0 + j];
            if (EPI == 1) v += cp[j];
            if (EPI == 2) v = 0.5f * v * (1.0f + erff(v * 0.70710678118654752f));
            cp[j] = v;
        }
    }
}

// ------------------------- fused attention ----------------------------------
// One block per (q-tile of 64, head, batch). t is Q=K=V (shared projection).
// Phase A: S[64x512] = Q Kt^T * scale + key_bias into SMEM
// Phase B: row softmax (two-pass, exact max)
// Phase C: O[64x64] = P V, scaled by 1/rowsum on store.
#define QK_STRIDE 68
#define SSTRIDE   520
#define SM_Q     0
#define SM_K     (64 * QK_STRIDE)
#define SM_S     (2 * 64 * QK_STRIDE)
#define SM_BIAS  (SM_S + 64 * SSTRIDE)
#define SM_LINV  (SM_BIAS + 512)
#define ATT_SMEM_FLOATS (SM_LINV + 64)

__global__ __launch_bounds__(256, 1)
void attn_kernel(const float* __restrict__ t, const int* __restrict__ masked,
                 float* __restrict__ o) {
    extern __shared__ float sm[];
    float* QsT   = sm + SM_Q;     // [d][q], stride 68
    float* Ks    = sm + SM_K;     // phase A: [d][k]; phase C: [k][d]
    float* Sm    = sm + SM_S;     // [q][512], stride 520
    float* biasS = sm + SM_BIAS;
    float* linv  = sm + SM_LINV;

    const int qt = blockIdx.x, h = blockIdx.y, b = blockIdx.z;
    const int tid = threadIdx.x;

    // key bias row
    for (int i = tid; i < 512; i += 256)
        biasS[i] = (masked[b * 512 + i] == 1) ? -1e9f : 0.0f;

    // load Q tile transposed: QsT[d][q]
    {
        int row = tid >> 2;
        int d0  = (tid & 3) * 16;
        const float* qp = t + ((size_t)(b * 512 + qt * 64 + row)) * DD + h * 64 + d0;
        #pragma unroll
        for (int i = 0; i < 16; i += 4) {
            float4 v = *(const float4*)(qp + i);
            QsT[(d0 + i + 0) * QK_STRIDE + row] = v.x;
            QsT[(d0 + i + 1) * QK_STRIDE + row] = v.y;
            QsT[(d0 + i + 2) * QK_STRIDE + row] = v.z;
            QsT[(d0 + i + 3) * QK_STRIDE + row] = v.w;
        }
    }

    const float scale = 0.125f;  // 1/sqrt(64)
    const int aty = tid >> 4, atx = tid & 15;

    // ---------------- Phase A: scores ----------------
    for (int kt = 0; kt < 8; kt++) {
        int row = tid >> 2;
        int d0  = (tid & 3) * 16;
        const float* kp = t + ((size_t)(b * 512 + kt * 64 + row)) * DD + h * 64 + d0;
        float4 r0 = *(const float4*)(kp + 0);
        float4 r1 = *(const float4*)(kp + 4);
        float4 r2 = *(const float4*)(kp + 8);
        float4 r3 = *(const float4*)(kp + 12);
        __syncthreads();
        Ks[(d0 + 0)  * QK_STRIDE + row] = r0.x;
        Ks[(d0 + 1)  * QK_STRIDE + row] = r0.y;
        Ks[(d0 + 2)  * QK_STRIDE + row] = r0.z;
        Ks[(d0 + 3)  * QK_STRIDE + row] = r0.w;
        Ks[(d0 + 4)  * QK_STRIDE + row] = r1.x;
        Ks[(d0 + 5)  * QK_STRIDE + row] = r1.y;
        Ks[(d0 + 6)  * QK_STRIDE + row] = r1.z;
        Ks[(d0 + 7)  * QK_STRIDE + row] = r1.w;
        Ks[(d0 + 8)  * QK_STRIDE + row] = r2.x;
        Ks[(d0 + 9)  * QK_STRIDE + row] = r2.y;
        Ks[(d0 + 10) * QK_STRIDE + row] = r2.z;
        Ks[(d0 + 11) * QK_STRIDE + row] = r2.w;
        Ks[(d0 + 12) * QK_STRIDE + row] = r3.x;
        Ks[(d0 + 13) * QK_STRIDE + row] = r3.y;
        Ks[(d0 + 14) * QK_STRIDE + row] = r3.z;
        Ks[(d0 + 15) * QK_STRIDE + row] = r3.w;
        __syncthreads();

        float acc[4][4];
        #pragma unroll
        for (int i = 0; i < 4; i++)
            #pragma unroll
            for (int j = 0; j < 4; j++) acc[i][j] = 0.f;
        #pragma unroll 4
        for (int d = 0; d < 64; d++) {
            float4 qa = *(const float4*)&QsT[d * QK_STRIDE + aty * 4];
            float4 ka = *(const float4*)&Ks [d * QK_STRIDE + atx * 4];
            float qv[4] = {qa.x, qa.y, qa.z, qa.w};
            float kv[4] = {ka.x, ka.y, ka.z, ka.w};
            #pragma unroll
            for (int i = 0; i < 4; i++)
                #pragma unroll
                for (int j = 0; j < 4; j++)
                    acc[i][j] += qv[i] * kv[j];
        }
        #pragma unroll
        for (int i = 0; i < 4; i++)
            #pragma unroll
            for (int j = 0; j < 4; j++) {
                int kg = kt * 64 + atx * 4 + j;
                Sm[(aty * 4 + i) * SSTRIDE + kg] = acc[i][j] * scale + biasS[kg];
            }
    }
    __syncthreads();

    // ---------------- Phase B: softmax ----------------
    {
        int row = tid >> 2, tg = tid & 3;
        float* srow = Sm + row * SSTRIDE;
        float m = -1e30f;
        for (int i = tg; i < 512; i += 4) m = fmaxf(m, srow[i]);
        m = fmaxf(m, __shfl_xor_sync(0xffffffffu, m, 1));
        m = fmaxf(m, __shfl_xor_sync(0xffffffffu, m, 2));
        float s = 0.f;
        for (int i = tg; i < 512; i += 4) {
            float e = expf(srow[i] - m);
            srow[i] = e;
            s += e;
        }
        s += __shfl_xor_sync(0xffffffffu, s, 1);
        s += __shfl_xor_sync(0xffffffffu, s, 2);
        if (tg == 0) linv[row] = 1.0f / s;
    }

    // ---------------- Phase C: O = P V ----------------
    float acc0[8], acc1[8];
    #pragma unroll
    for (int j = 0; j < 8; j++) { acc0[j] = 0.f; acc1[j] = 0.f; }
    const int rp = tid >> 3;          // 0..31 -> rows rp and rp+32
    const int c0 = (tid & 7) * 8;     // 8 d-cols

    for (int kt = 0; kt < 8; kt++) {
        int row = tid >> 2;
        int d0  = (tid & 3) * 16;
        const float* kp = t + ((size_t)(b * 512 + kt * 64 + row)) * DD + h * 64 + d0;
        float4 r0 = *(const float4*)(kp + 0);
        float4 r1 = *(const float4*)(kp + 4);
        float4 r2 = *(const float4*)(kp + 8);
        float4 r3 = *(const float4*)(kp + 12);
        __syncthreads();
        *(float4*)&Ks[row * QK_STRIDE + d0 + 0]  = r0;
        *(float4*)&Ks[row * QK_STRIDE + d0 + 4]  = r1;
        *(float4*)&Ks[row * QK_STRIDE + d0 + 8]  = r2;
        *(float4*)&Ks[row * QK_STRIDE + d0 + 12] = r3;
        __syncthreads();

        const float* p0 = Sm + rp * SSTRIDE + kt * 64;
        const float* p1 = Sm + (rp + 32) * SSTRIDE + kt * 64;
        #pragma unroll 4
        for (int k = 0; k < 64; k++) {
            float w0 = p0[k];
            float w1 = p1[k];
            float4 v0 = *(const float4*)&Ks[k * QK_STRIDE + c0];
            float4 v1 = *(const float4*)&Ks[k * QK_STRIDE + c0 + 4];
            acc0[0] += w0 * v0.x; acc0[1] += w0 * v0.y;
            acc0[2] += w0 * v0.z; acc0[3] += w0 * v0.w;
            acc0[4] += w0 * v1.x; acc0[5] += w0 * v1.y;
            acc0[6] += w0 * v1.z; acc0[7] += w0 * v1.w;
            acc1[0] += w1 * v0.x; acc1[1] += w1 * v0.y;
            acc1[2] += w1 * v0.z; acc1[3] += w1 * v0.w;
            acc1[4] += w1 * v1.x; acc1[5] += w1 * v1.y;
            acc1[6] += w1 * v1.z; acc1[7] += w1 * v1.w;
        }
    }

    float l0 = linv[rp], l1 = linv[rp + 32];
    float* op0 = o + ((size_t)(b * 512 + qt * 64 + rp)) * DD + h * 64 + c0;
    float* op1 = o + ((size_t)(b * 512 + qt * 64 + rp + 32)) * DD + h * 64 + c0;
    float4 w;
    w.x = acc0[0] * l0; w.y = acc0[1] * l0; w.z = acc0[2] * l0; w.w = acc0[3] * l0;
    *(float4*)(op0 + 0) = w;
    w.x = acc0[4] * l0; w.y = acc0[5] * l0; w.z = acc0[6] * l0; w.w = acc0[7] * l0;
    *(float4*)(op0 + 4) = w;
    w.x = acc1[0] * l1; w.y = acc1[1] * l1; w.z = acc1[2] * l1; w.w = acc1[3] * l1;
    *(float4*)(op1 + 0) = w;
    w.x = acc1[4] * l1; w.y = acc1[5] * l1; w.z = acc1[6] * l1; w.w = acc1[7] * l1;
    *(float4*)(op1 + 4) = w;
}

// ------------------------- host orchestration --------------------------------
extern "C" void kernel_launch(void* const* d_in, const int* in_sizes, int n_in,
                              void* d_out, int out_size) {
    const int*   masked = (const int*)  d_in[0];
    const float* tok    = (const float*)d_in[1];
    const float* seg    = (const float*)d_in[2];
    const float* ln1s   = (const float*)d_in[3];
    const float* ln1b   = (const float*)d_in[4];
    const float* wq     = (const float*)d_in[5];
    const float* bq     = (const float*)d_in[6];
    const float* wo     = (const float*)d_in[7];
    const float* bo     = (const float*)d_in[8];
    const float* ln2s   = (const float*)d_in[9];
    const float* ln2b   = (const float*)d_in[10];
    const float* w1     = (const float*)d_in[11];
    const float* b1     = (const float*)d_in[12];
    const float* w2     = (const float*)d_in[13];
    const float* b2     = (const float*)d_in[14];
    float* x = (float*)d_out;

    float *xn, *tt, *oo, *hh;
    cudaGetSymbolAddress((void**)&xn, g_xn);
    cudaGetSymbolAddress((void**)&tt, g_t);
    cudaGetSymbolAddress((void**)&oo, g_o);
    cudaGetSymbolAddress((void**)&hh, g_h);

    const size_t ATT_SMEM = ATT_SMEM_FLOATS * sizeof(float);
    cudaFuncSetAttribute(attn_kernel, cudaFuncAttributeMaxDynamicSharedMemorySize,
                         (int)ATT_SMEM);

    embed_kernel<<<ROWS, 256>>>(masked, tok, seg, x);

    for (int l = 0; l < LL; l++) {
        const float* wql = wq + (size_t)l * DD * DD;
        const float* wol = wo + (size_t)l * DD * DD;
        const float* w1l = w1 + (size_t)l * DD * DFFN;
        const float* w2l = w2 + (size_t)l * DFFN * DD;

        ln_kernel<<<ROWS, 256>>>(x, ln1s + l * DD, ln1b + l * DD, xn);
        gemm_kernel<0><<<dim3(DD / 128, ROWS / 128), 256>>>(
            xn, wql, bq + l * DD, tt, ROWS, DD, DD);
        attn_kernel<<<dim3(8, HH, BB), 256, ATT_SMEM>>>(tt, masked, oo);
        gemm_kernel<1><<<dim3(DD / 128, ROWS / 128), 256>>>(
            oo, wol, bo + l * DD, x, ROWS, DD, DD);
        ln_kernel<<<ROWS, 256>>>(x, ln2s + l * DD, ln2b + l * DD, xn);
        gemm_kernel<2><<<dim3(DFFN / 128, ROWS / 128), 256>>>(
            xn, w1l, b1 + l * DFFN, hh, ROWS, DFFN, DD);
        gemm_kernel<1><<<dim3(DD / 128, ROWS / 128), 256>>>(
            hh, w2l, b2 + l * DD, x, ROWS, DD, DFFN);
    }
}

// round 3
// speedup vs baseline: 1.8821x; 1.8821x over previous
#include <cuda_runtime.h>
#include <math.h>
#include <stdint.h>

#define BB 16
#define SS_ 512
#define DD 1024
#define HH 16
#define LL 12
#define DKK 64
#define DFFN 4096
#define ROWS (BB*SS_)   // 8192

// ------------------------- scratch (static device memory) -------------------
__device__ float g_xn[ROWS * DD];     // LN output
__device__ float g_t [ROWS * DD];     // shared QKV projection t
__device__ float g_o [ROWS * DD];     // attention output
__device__ float g_h [ROWS * DFFN];   // FFN hidden

// ------------------------- embedding + positional encoding ------------------
__global__ void embed_kernel(const int* __restrict__ masked,
                             const float* __restrict__ tok,
                             const float* __restrict__ seg,
                             float* __restrict__ x) {
    int bs = blockIdx.x;
    int s  = bs & (SS_ - 1);
    int id = masked[bs];
    const float* tp = tok + (size_t)id * DD;
    const float* sp = seg + DD;          // seg_emb[1]
    int j = threadIdx.x * 4;
    const float L = 0.0089944730328f;    // ln(10000)/1024
    float f0 = expf(-(float)j * L);
    float f1 = expf(-(float)(j + 2) * L);
    float a0 = (float)s * f0;
    float a1 = (float)s * f1;
    float4 tv = *(const float4*)(tp + j);
    float4 sv = *(const float4*)(sp + j);
    float4 r;
    r.x = tv.x + sinf(a0) + sv.x;
    r.y = tv.y + cosf(a0) + sv.y;
    r.z = tv.z + sinf(a1) + sv.z;
    r.w = tv.w + cosf(a1) + sv.w;
    *(float4*)(x + (size_t)bs * DD + j) = r;
}

// ------------------------- layernorm ---------------------------------------
__global__ void ln_kernel(const float* __restrict__ x,
                          const float* __restrict__ gamma,
                          const float* __restrict__ beta,
                          float* __restrict__ y) {
    int row = blockIdx.x;
    int tid = threadIdx.x;               // 256
    const float4* xp = (const float4*)(x + (size_t)row * DD);
    float4 v = xp[tid];
    float s = v.x + v.y + v.z + v.w;
    float q = v.x*v.x + v.y*v.y + v.z*v.z + v.w*v.w;
    #pragma unroll
    for (int o = 16; o > 0; o >>= 1) {
        s += __shfl_down_sync(0xffffffffu, s, o);
        q += __shfl_down_sync(0xffffffffu, q, o);
    }
    __shared__ float ss[8], qs[8];
    __shared__ float mu, rstd;
    int wid = tid >> 5, lane = tid & 31;
    if (lane == 0) { ss[wid] = s; qs[wid] = q; }
    __syncthreads();
    if (tid == 0) {
        float S = 0.f, Q = 0.f;
        #pragma unroll
        for (int i = 0; i < 8; i++) { S += ss[i]; Q += qs[i]; }
        float m = S * (1.0f / DD);
        mu = m;
        rstd = rsqrtf(Q * (1.0f / DD) - m * m + 1e-5f);
    }
    __syncthreads();
    int j = tid * 4;
    float4 g  = *(const float4*)(gamma + j);
    float4 bt = *(const float4*)(beta + j);
    float m = mu, r = rstd;
    float4 out;
    out.x = (v.x - m) * r * g.x + bt.x;
    out.y = (v.y - m) * r * g.y + bt.y;
    out.z = (v.z - m) * r * g.z + bt.z;
    out.w = (v.w - m) * r * g.w + bt.w;
    *(float4*)(y + (size_t)row * DD + j) = out;
}

// ------------------------- TF32 tensor-core GEMM -----------------------------
// C[M,N] = A[M,K] * B[K,N]  (row-major), fp32 accum, tf32 inputs (rna-rounded).
// CTA tile 128x128, k-tile 32, 8 warps, warp tile 64x32 (4x4 m16n8k8 frags).
// EPI: 0 = bias, 1 = bias + residual (C in-place), 2 = bias + exact GELU.

#define A_STRIDE 36    // [m][k] padded
#define B_STRIDE 132   // [k][n] padded
#define A_BUF (128 * A_STRIDE)
#define B_BUF (32 * B_STRIDE)
#define GEMM_SMEM_FLOATS (2 * A_BUF + 2 * B_BUF)

__device__ __forceinline__ float to_tf32(float x) {
    uint32_t o;
    asm("cvt.rna.tf32.f32 %0, %1;" : "=r"(o) : "f"(x));
    return __uint_as_float(o);
}

__device__ __forceinline__ void mma_tf32(float c[4],
                                         uint32_t a0, uint32_t a1, uint32_t a2, uint32_t a3,
                                         uint32_t b0, uint32_t b1) {
    asm volatile(
        "mma.sync.aligned.m16n8k8.row.col.f32.tf32.tf32.f32 "
        "{%0,%1,%2,%3},{%4,%5,%6,%7},{%8,%9},{%0,%1,%2,%3};"
        : "+f"(c[0]), "+f"(c[1]), "+f"(c[2]), "+f"(c[3])
        : "r"(a0), "r"(a1), "r"(a2), "r"(a3), "r"(b0), "r"(b1));
}

template <int EPI>
__global__ __launch_bounds__(256)
void gemm_tf32_kernel(const float* __restrict__ A, const float* __restrict__ B,
                      const float* __restrict__ bias, float* __restrict__ C,
                      int M, int N, int K) {
    extern __shared__ float sm[];
    float* As = sm;                 // [2][128][A_STRIDE]
    float* Bs = sm + 2 * A_BUF;     // [2][32][B_STRIDE]

    const int tid  = threadIdx.x;
    const int lane = tid & 31;
    const int warp = tid >> 5;
    const int wm = (warp & 1) * 64;     // warp row offset in CTA tile
    const int wn = (warp >> 1) * 32;    // warp col offset
    const int bm = blockIdx.y, bn = blockIdx.x;

    // global load indexing
    const int aRow = tid >> 3;          // 0..31 (4 passes of 32 rows)
    const int aCol = (tid & 7) * 4;     // 0..28
    const int bRow = tid >> 5;          // 0..7 (4 passes of 8 rows)
    const int bCol = (tid & 31) * 4;    // 0..124
    const float* Ag = A + (size_t)(bm * 128) * K;
    const float* Bg = B + bn * 128;

    float4 aReg[4], bReg[4];
    float acc[4][4][4];
    #pragma unroll
    for (int i = 0; i < 4; i++)
        #pragma unroll
        for (int j = 0; j < 4; j++)
            #pragma unroll
            for (int r = 0; r < 4; r++) acc[i][j][r] = 0.f;

    const int ntiles = K >> 5;

    // ---- prologue: load tile 0 into regs, store to smem buf 0 ----
    #pragma unroll
    for (int i = 0; i < 4; i++)
        aReg[i] = *(const float4*)(Ag + (size_t)(aRow + 32 * i) * K + aCol);
    #pragma unroll
    for (int i = 0; i < 4; i++)
        bReg[i] = *(const float4*)(Bg + (size_t)(bRow + 8 * i) * N + bCol);
    #pragma unroll
    for (int i = 0; i < 4; i++) {
        float* p = As + (aRow + 32 * i) * A_STRIDE + aCol;
        p[0] = to_tf32(aReg[i].x); p[1] = to_tf32(aReg[i].y);
        p[2] = to_tf32(aReg[i].z); p[3] = to_tf32(aReg[i].w);
    }
    #pragma unroll
    for (int i = 0; i < 4; i++) {
        float* p = Bs + (bRow + 8 * i) * B_STRIDE + bCol;
        p[0] = to_tf32(bReg[i].x); p[1] = to_tf32(bReg[i].y);
        p[2] = to_tf32(bReg[i].z); p[3] = to_tf32(bReg[i].w);
    }
    __syncthreads();

    int cur = 0;
    for (int kt = 0; kt < ntiles; kt++) {
        // prefetch next tile into registers
        if (kt + 1 < ntiles) {
            const float* Agk = Ag + (kt + 1) * 32;
            const float* Bgk = Bg + (size_t)((kt + 1) * 32) * N;
            #pragma unroll
            for (int i = 0; i < 4; i++)
                aReg[i] = *(const float4*)(Agk + (size_t)(aRow + 32 * i) * K + aCol);
            #pragma unroll
            for (int i = 0; i < 4; i++)
                bReg[i] = *(const float4*)(Bgk + (size_t)(bRow + 8 * i) * N + bCol);
        }

        // compute on current buffer
        const float* Ab = As + cur * A_BUF;
        const float* Bb = Bs + cur * B_BUF;
        #pragma unroll
        for (int kk = 0; kk < 32; kk += 8) {
            uint32_t af[4][4];
            uint32_t bf[4][2];
            #pragma unroll
            for (int mi = 0; mi < 4; mi++) {
                const float* p = Ab + (wm + mi * 16 + (lane >> 2)) * A_STRIDE + kk + (lane & 3);
                af[mi][0] = __float_as_uint(p[0]);
                af[mi][1] = __float_as_uint(p[8 * A_STRIDE]);
                af[mi][2] = __float_as_uint(p[4]);
                af[mi][3] = __float_as_uint(p[8 * A_STRIDE + 4]);
            }
            #pragma unroll
            for (int nj = 0; nj < 4; nj++) {
                const float* p = Bb + (kk + (lane & 3)) * B_STRIDE + wn + nj * 8 + (lane >> 2);
                bf[nj][0] = __float_as_uint(p[0]);
                bf[nj][1] = __float_as_uint(p[4 * B_STRIDE]);
            }
            #pragma unroll
            for (int mi = 0; mi < 4; mi++)
                #pragma unroll
                for (int nj = 0; nj < 4; nj++)
                    mma_tf32(acc[mi][nj], af[mi][0], af[mi][1], af[mi][2], af[mi][3],
                             bf[nj][0], bf[nj][1]);
        }

        if (kt + 1 < ntiles) {
            __syncthreads();
            float* Ao = As + (cur ^ 1) * A_BUF;
            float* Bo = Bs + (cur ^ 1) * B_BUF;
            #pragma unroll
            for (int i = 0; i < 4; i++) {
                float* p = Ao + (aRow + 32 * i) * A_STRIDE + aCol;
                p[0] = to_tf32(aReg[i].x); p[1] = to_tf32(aReg[i].y);
                p[2] = to_tf32(aReg[i].z); p[3] = to_tf32(aReg[i].w);
            }
            #pragma unroll
            for (int i = 0; i < 4; i++) {
                float* p = Bo + (bRow + 8 * i) * B_STRIDE + bCol;
                p[0] = to_tf32(bReg[i].x); p[1] = to_tf32(bReg[i].y);
                p[2] = to_tf32(bReg[i].z); p[3] = to_tf32(bReg[i].w);
            }
            __syncthreads();
            cur ^= 1;
        }
    }

    // ---- epilogue ----
    const int row0 = bm * 128 + wm + (lane >> 2);
    const int col0 = bn * 128 + wn + 2 * (lane & 3);
    #pragma unroll
    for (int mi = 0; mi < 4; mi++) {
        #pragma unroll
        for (int nj = 0; nj < 4; nj++) {
            int c = col0 + nj * 8;
            float2 bv = *(const float2*)(bias + c);
            #pragma unroll
            for (int half = 0; half < 2; half++) {
                int r = row0 + mi * 16 + half * 8;
                float* cp = C + (size_t)r * N + c;
                float v0 = acc[mi][nj][half * 2 + 0] + bv.x;
                float v1 = acc[mi][nj][half * 2 + 1] + bv.y;
                if (EPI == 1) { float2 rv = *(const float2*)cp; v0 += rv.x; v1 += rv.y; }
                if (EPI == 2) {
                    v0 = 0.5f * v0 * (1.0f + erff(v0 * 0.70710678118654752f));
                    v1 = 0.5f * v1 * (1.0f + erff(v1 * 0.70710678118654752f));
                }
                float2 w; w.x = v0; w.y = v1;
                *(float2*)cp = w;
            }
        }
    }
}

// ------------------------- fused attention ----------------------------------
#define QK_STRIDE 68
#define SSTRIDE   520
#define SM_Q     0
#define SM_K     (64 * QK_STRIDE)
#define SM_S     (2 * 64 * QK_STRIDE)
#define SM_BIAS  (SM_S + 64 * SSTRIDE)
#define SM_LINV  (SM_BIAS + 512)
#define ATT_SMEM_FLOATS (SM_LINV + 64)

__global__ __launch_bounds__(256, 1)
void attn_kernel(const float* __restrict__ t, const int* __restrict__ masked,
                 float* __restrict__ o) {
    extern __shared__ float sm[];
    float* QsT   = sm + SM_Q;
    float* Ks    = sm + SM_K;
    float* Sm    = sm + SM_S;
    float* biasS = sm + SM_BIAS;
    float* linv  = sm + SM_LINV;

    const int qt = blockIdx.x, h = blockIdx.y, b = blockIdx.z;
    const int tid = threadIdx.x;

    for (int i = tid; i < 512; i += 256)
        biasS[i] = (masked[b * 512 + i] == 1) ? -1e9f : 0.0f;

    {
        int row = tid >> 2;
        int d0  = (tid & 3) * 16;
        const float* qp = t + ((size_t)(b * 512 + qt * 64 + row)) * DD + h * 64 + d0;
        #pragma unroll
        for (int i = 0; i < 16; i += 4) {
            float4 v = *(const float4*)(qp + i);
            QsT[(d0 + i + 0) * QK_STRIDE + row] = v.x;
            QsT[(d0 + i + 1) * QK_STRIDE + row] = v.y;
            QsT[(d0 + i + 2) * QK_STRIDE + row] = v.z;
            QsT[(d0 + i + 3) * QK_STRIDE + row] = v.w;
        }
    }

    const float scale = 0.125f;
    const int aty = tid >> 4, atx = tid & 15;

    for (int kt = 0; kt < 8; kt++) {
        int row = tid >> 2;
        int d0  = (tid & 3) * 16;
        const float* kp = t + ((size_t)(b * 512 + kt * 64 + row)) * DD + h * 64 + d0;
        float4 r0 = *(const float4*)(kp + 0);
        float4 r1 = *(const float4*)(kp + 4);
        float4 r2 = *(const float4*)(kp + 8);
        float4 r3 = *(const float4*)(kp + 12);
        __syncthreads();
        Ks[(d0 + 0)  * QK_STRIDE + row] = r0.x;
        Ks[(d0 + 1)  * QK_STRIDE + row] = r0.y;
        Ks[(d0 + 2)  * QK_STRIDE + row] = r0.z;
        Ks[(d0 + 3)  * QK_STRIDE + row] = r0.w;
        Ks[(d0 + 4)  * QK_STRIDE + row] = r1.x;
        Ks[(d0 + 5)  * QK_STRIDE + row] = r1.y;
        Ks[(d0 + 6)  * QK_STRIDE + row] = r1.z;
        Ks[(d0 + 7)  * QK_STRIDE + row] = r1.w;
        Ks[(d0 + 8)  * QK_STRIDE + row] = r2.x;
        Ks[(d0 + 9)  * QK_STRIDE + row] = r2.y;
        Ks[(d0 + 10) * QK_STRIDE + row] = r2.z;
        Ks[(d0 + 11) * QK_STRIDE + row] = r2.w;
        Ks[(d0 + 12) * QK_STRIDE + row] = r3.x;
        Ks[(d0 + 13) * QK_STRIDE + row] = r3.y;
        Ks[(d0 + 14) * QK_STRIDE + row] = r3.z;
        Ks[(d0 + 15) * QK_STRIDE + row] = r3.w;
        __syncthreads();

        float acc[4][4];
        #pragma unroll
        for (int i = 0; i < 4; i++)
            #pragma unroll
            for (int j = 0; j < 4; j++) acc[i][j] = 0.f;
        #pragma unroll 4
        for (int d = 0; d < 64; d++) {
            float4 qa = *(const float4*)&QsT[d * QK_STRIDE + aty * 4];
            float4 ka = *(const float4*)&Ks [d * QK_STRIDE + atx * 4];
            float qv[4] = {qa.x, qa.y, qa.z, qa.w};
            float kv[4] = {ka.x, ka.y, ka.z, ka.w};
            #pragma unroll
            for (int i = 0; i < 4; i++)
                #pragma unroll
                for (int j = 0; j < 4; j++)
                    acc[i][j] += qv[i] * kv[j];
        }
        #pragma unroll
        for (int i = 0; i < 4; i++)
            #pragma unroll
            for (int j = 0; j < 4; j++) {
                int kg = kt * 64 + atx * 4 + j;
                Sm[(aty * 4 + i) * SSTRIDE + kg] = acc[i][j] * scale + biasS[kg];
            }
    }
    __syncthreads();

    {
        int row = tid >> 2, tg = tid & 3;
        float* srow = Sm + row * SSTRIDE;
        float m = -1e30f;
        for (int i = tg; i < 512; i += 4) m = fmaxf(m, srow[i]);
        m = fmaxf(m, __shfl_xor_sync(0xffffffffu, m, 1));
        m = fmaxf(m, __shfl_xor_sync(0xffffffffu, m, 2));
        float s = 0.f;
        for (int i = tg; i < 512; i += 4) {
            float e = expf(srow[i] - m);
            srow[i] = e;
            s += e;
        }
        s += __shfl_xor_sync(0xffffffffu, s, 1);
        s += __shfl_xor_sync(0xffffffffu, s, 2);
        if (tg == 0) linv[row] = 1.0f / s;
    }

    float acc0[8], acc1[8];
    #pragma unroll
    for (int j = 0; j < 8; j++) { acc0[j] = 0.f; acc1[j] = 0.f; }
    const int rp = tid >> 3;
    const int c0 = (tid & 7) * 8;

    for (int kt = 0; kt < 8; kt++) {
        int row = tid >> 2;
        int d0  = (tid & 3) * 16;
        const float* kp = t + ((size_t)(b * 512 + kt * 64 + row)) * DD + h * 64 + d0;
        float4 r0 = *(const float4*)(kp + 0);
        float4 r1 = *(const float4*)(kp + 4);
        float4 r2 = *(const float4*)(kp + 8);
        float4 r3 = *(const float4*)(kp + 12);
        __syncthreads();
        *(float4*)&Ks[row * QK_STRIDE + d0 + 0]  = r0;
        *(float4*)&Ks[row * QK_STRIDE + d0 + 4]  = r1;
        *(float4*)&Ks[row * QK_STRIDE + d0 + 8]  = r2;
        *(float4*)&Ks[row * QK_STRIDE + d0 + 12] = r3;
        __syncthreads();

        const float* p0 = Sm + rp * SSTRIDE + kt * 64;
        const float* p1 = Sm + (rp + 32) * SSTRIDE + kt * 64;
        #pragma unroll 4
        for (int k = 0; k < 64; k++) {
            float w0 = p0[k];
            float w1 = p1[k];
            float4 v0 = *(const float4*)&Ks[k * QK_STRIDE + c0];
            float4 v1 = *(const float4*)&Ks[k * QK_STRIDE + c0 + 4];
            acc0[0] += w0 * v0.x; acc0[1] += w0 * v0.y;
            acc0[2] += w0 * v0.z; acc0[3] += w0 * v0.w;
            acc0[4] += w0 * v1.x; acc0[5] += w0 * v1.y;
            acc0[6] += w0 * v1.z; acc0[7] += w0 * v1.w;
            acc1[0] += w1 * v0.x; acc1[1] += w1 * v0.y;
            acc1[2] += w1 * v0.z; acc1[3] += w1 * v0.w;
            acc1[4] += w1 * v1.x; acc1[5] += w1 * v1.y;
            acc1[6] += w1 * v1.z; acc1[7] += w1 * v1.w;
        }
    }

    float l0 = linv[rp], l1 = linv[rp + 32];
    float* op0 = o + ((size_t)(b * 512 + qt * 64 + rp)) * DD + h * 64 + c0;
    float* op1 = o + ((size_t)(b * 512 + qt * 64 + rp + 32)) * DD + h * 64 + c0;
    float4 w;
    w.x = acc0[0] * l0; w.y = acc0[1] * l0; w.z = acc0[2] * l0; w.w = acc0[3] * l0;
    *(float4*)(op0 + 0) = w;
    w.x = acc0[4] * l0; w.y = acc0[5] * l0; w.z = acc0[6] * l0; w.w = acc0[7] * l0;
    *(float4*)(op0 + 4) = w;
    w.x = acc1[0] * l1; w.y = acc1[1] * l1; w.z = acc1[2] * l1; w.w = acc1[3] * l1;
    *(float4*)(op1 + 0) = w;
    w.x = acc1[4] * l1; w.y = acc1[5] * l1; w.z = acc1[6] * l1; w.w = acc1[7] * l1;
    *(float4*)(op1 + 4) = w;
}

// ------------------------- host orchestration --------------------------------
extern "C" void kernel_launch(void* const* d_in, const int* in_sizes, int n_in,
                              void* d_out, int out_size) {
    const int*   masked = (const int*)  d_in[0];
    const float* tok    = (const float*)d_in[1];
    const float* seg    = (const float*)d_in[2];
    const float* ln1s   = (const float*)d_in[3];
    const float* ln1b   = (const float*)d_in[4];
    const float* wq     = (const float*)d_in[5];
    const float* bq     = (const float*)d_in[6];
    const float* wo     = (const float*)d_in[7];
    const float* bo     = (const float*)d_in[8];
    const float* ln2s   = (const float*)d_in[9];
    const float* ln2b   = (const float*)d_in[10];
    const float* w1     = (const float*)d_in[11];
    const float* b1     = (const float*)d_in[12];
    const float* w2     = (const float*)d_in[13];
    const float* b2     = (const float*)d_in[14];
    float* x = (float*)d_out;

    float *xn, *tt, *oo, *hh;
    cudaGetSymbolAddress((void**)&xn, g_xn);
    cudaGetSymbolAddress((void**)&tt, g_t);
    cudaGetSymbolAddress((void**)&oo, g_o);
    cudaGetSymbolAddress((void**)&hh, g_h);

    const size_t ATT_SMEM  = ATT_SMEM_FLOATS * sizeof(float);
    const size_t GEMM_SMEM = GEMM_SMEM_FLOATS * sizeof(float);
    cudaFuncSetAttribute(attn_kernel, cudaFuncAttributeMaxDynamicSharedMemorySize,
                         (int)ATT_SMEM);
    cudaFuncSetAttribute(gemm_tf32_kernel<0>, cudaFuncAttributeMaxDynamicSharedMemorySize,
                         (int)GEMM_SMEM);
    cudaFuncSetAttribute(gemm_tf32_kernel<1>, cudaFuncAttributeMaxDynamicSharedMemorySize,
                         (int)GEMM_SMEM);
    cudaFuncSetAttribute(gemm_tf32_kernel<2>, cudaFuncAttributeMaxDynamicSharedMemorySize,
                         (int)GEMM_SMEM);

    embed_kernel<<<ROWS, 256>>>(masked, tok, seg, x);

    for (int l = 0; l < LL; l++) {
        const float* wql = wq + (size_t)l * DD * DD;
        const float* wol = wo + (size_t)l * DD * DD;
        const float* w1l = w1 + (size_t)l * DD * DFFN;
        const float* w2l = w2 + (size_t)l * DFFN * DD;

        ln_kernel<<<ROWS, 256>>>(x, ln1s + l * DD, ln1b + l * DD, xn);
        gemm_tf32_kernel<0><<<dim3(DD / 128, ROWS / 128), 256, GEMM_SMEM>>>(
            xn, wql, bq + l * DD, tt, ROWS, DD, DD);
        attn_kernel<<<dim3(8, HH, BB), 256, ATT_SMEM>>>(tt, masked, oo);
        gemm_tf32_kernel<1><<<dim3(DD / 128, ROWS / 128), 256, GEMM_SMEM>>>(
            oo, wol, bo + l * DD, x, ROWS, DD, DD);
        ln_kernel<<<ROWS, 256>>>(x, ln2s + l * DD, ln2b + l * DD, xn);
        gemm_tf32_kernel<2><<<dim3(DFFN / 128, ROWS / 128), 256, GEMM_SMEM>>>(
            xn, w1l, b1 + l * DFFN, hh, ROWS, DFFN, DD);
        gemm_tf32_kernel<1><<<dim3(DD / 128, ROWS / 128), 256, GEMM_SMEM>>>(
            hh, w2l, b2 + l * DD, x, ROWS, DD, DFFN);
    }
}

// round 4
// speedup vs baseline: 2.0328x; 1.0801x over previous
#include <cuda_runtime.h>
#include <math.h>
#include <stdint.h>

#define BB 16
#define SS_ 512
#define DD 1024
#define HH 16
#define LL 12
#define DKK 64
#define DFFN 4096
#define ROWS (BB*SS_)   // 8192

// ------------------------- scratch (static device memory) -------------------
__device__ float g_xn[ROWS * DD];     // LN output
__device__ float g_t [ROWS * DD];     // shared QKV projection t
__device__ float g_o [ROWS * DD];     // attention output
__device__ float g_h [ROWS * DFFN];   // FFN hidden

// ------------------------- embedding + positional encoding ------------------
__global__ void embed_kernel(const int* __restrict__ masked,
                             const float* __restrict__ tok,
                             const float* __restrict__ seg,
                             float* __restrict__ x) {
    int bs = blockIdx.x;
    int s  = bs & (SS_ - 1);
    int id = masked[bs];
    const float* tp = tok + (size_t)id * DD;
    const float* sp = seg + DD;          // seg_emb[1]
    int j = threadIdx.x * 4;
    const float L = 0.0089944730328f;    // ln(10000)/1024
    float f0 = expf(-(float)j * L);
    float f1 = expf(-(float)(j + 2) * L);
    float a0 = (float)s * f0;
    float a1 = (float)s * f1;
    float4 tv = *(const float4*)(tp + j);
    float4 sv = *(const float4*)(sp + j);
    float4 r;
    r.x = tv.x + sinf(a0) + sv.x;
    r.y = tv.y + cosf(a0) + sv.y;
    r.z = tv.z + sinf(a1) + sv.z;
    r.w = tv.w + cosf(a1) + sv.w;
    *(float4*)(x + (size_t)bs * DD + j) = r;
}

// ------------------------- layernorm ---------------------------------------
__global__ void ln_kernel(const float* __restrict__ x,
                          const float* __restrict__ gamma,
                          const float* __restrict__ beta,
                          float* __restrict__ y) {
    int row = blockIdx.x;
    int tid = threadIdx.x;               // 256
    const float4* xp = (const float4*)(x + (size_t)row * DD);
    float4 v = xp[tid];
    float s = v.x + v.y + v.z + v.w;
    float q = v.x*v.x + v.y*v.y + v.z*v.z + v.w*v.w;
    #pragma unroll
    for (int o = 16; o > 0; o >>= 1) {
        s += __shfl_down_sync(0xffffffffu, s, o);
        q += __shfl_down_sync(0xffffffffu, q, o);
    }
    __shared__ float ss[8], qs[8];
    __shared__ float mu, rstd;
    int wid = tid >> 5, lane = tid & 31;
    if (lane == 0) { ss[wid] = s; qs[wid] = q; }
    __syncthreads();
    if (tid == 0) {
        float S = 0.f, Q = 0.f;
        #pragma unroll
        for (int i = 0; i < 8; i++) { S += ss[i]; Q += qs[i]; }
        float m = S * (1.0f / DD);
        mu = m;
        rstd = rsqrtf(Q * (1.0f / DD) - m * m + 1e-5f);
    }
    __syncthreads();
    int j = tid * 4;
    float4 g  = *(const float4*)(gamma + j);
    float4 bt = *(const float4*)(beta + j);
    float m = mu, r = rstd;
    float4 out;
    out.x = (v.x - m) * r * g.x + bt.x;
    out.y = (v.y - m) * r * g.y + bt.y;
    out.z = (v.z - m) * r * g.z + bt.z;
    out.w = (v.w - m) * r * g.w + bt.w;
    *(float4*)(y + (size_t)row * DD + j) = out;
}

// ------------------------- TF32 tensor-core GEMM -----------------------------
#define A_STRIDE 36    // [m][k] padded
#define B_STRIDE 132   // [k][n] padded
#define A_BUF (128 * A_STRIDE)
#define B_BUF (32 * B_STRIDE)
#define GEMM_SMEM_FLOATS (2 * A_BUF + 2 * B_BUF)

__device__ __forceinline__ float to_tf32(float x) {
    uint32_t o;
    asm("cvt.rna.tf32.f32 %0, %1;" : "=r"(o) : "f"(x));
    return __uint_as_float(o);
}

__device__ __forceinline__ void mma_tf32(float c[4],
                                         uint32_t a0, uint32_t a1, uint32_t a2, uint32_t a3,
                                         uint32_t b0, uint32_t b1) {
    asm volatile(
        "mma.sync.aligned.m16n8k8.row.col.f32.tf32.tf32.f32 "
        "{%0,%1,%2,%3},{%4,%5,%6,%7},{%8,%9},{%0,%1,%2,%3};"
        : "+f"(c[0]), "+f"(c[1]), "+f"(c[2]), "+f"(c[3])
        : "r"(a0), "r"(a1), "r"(a2), "r"(a3), "r"(b0), "r"(b1));
}

template <int EPI>
__global__ __launch_bounds__(256)
void gemm_tf32_kernel(const float* __restrict__ A, const float* __restrict__ B,
                      const float* __restrict__ bias, float* __restrict__ C,
                      int M, int N, int K) {
    extern __shared__ float sm[];
    float* As = sm;                 // [2][128][A_STRIDE]
    float* Bs = sm + 2 * A_BUF;     // [2][32][B_STRIDE]

    const int tid  = threadIdx.x;
    const int lane = tid & 31;
    const int warp = tid >> 5;
    const int wm = (warp & 1) * 64;
    const int wn = (warp >> 1) * 32;
    const int bm = blockIdx.y, bn = blockIdx.x;

    const int aRow = tid >> 3;
    const int aCol = (tid & 7) * 4;
    const int bRow = tid >> 5;
    const int bCol = (tid & 31) * 4;
    const float* Ag = A + (size_t)(bm * 128) * K;
    const float* Bg = B + bn * 128;

    float4 aReg[4], bReg[4];
    float acc[4][4][4];
    #pragma unroll
    for (int i = 0; i < 4; i++)
        #pragma unroll
        for (int j = 0; j < 4; j++)
            #pragma unroll
            for (int r = 0; r < 4; r++) acc[i][j][r] = 0.f;

    const int ntiles = K >> 5;

    #pragma unroll
    for (int i = 0; i < 4; i++)
        aReg[i] = *(const float4*)(Ag + (size_t)(aRow + 32 * i) * K + aCol);
    #pragma unroll
    for (int i = 0; i < 4; i++)
        bReg[i] = *(const float4*)(Bg + (size_t)(bRow + 8 * i) * N + bCol);
    #pragma unroll
    for (int i = 0; i < 4; i++) {
        float* p = As + (aRow + 32 * i) * A_STRIDE + aCol;
        p[0] = to_tf32(aReg[i].x); p[1] = to_tf32(aReg[i].y);
        p[2] = to_tf32(aReg[i].z); p[3] = to_tf32(aReg[i].w);
    }
    #pragma unroll
    for (int i = 0; i < 4; i++) {
        float* p = Bs + (bRow + 8 * i) * B_STRIDE + bCol;
        p[0] = to_tf32(bReg[i].x); p[1] = to_tf32(bReg[i].y);
        p[2] = to_tf32(bReg[i].z); p[3] = to_tf32(bReg[i].w);
    }
    __syncthreads();

    int cur = 0;
    for (int kt = 0; kt < ntiles; kt++) {
        if (kt + 1 < ntiles) {
            const float* Agk = Ag + (kt + 1) * 32;
            const float* Bgk = Bg + (size_t)((kt + 1) * 32) * N;
            #pragma unroll
            for (int i = 0; i < 4; i++)
                aReg[i] = *(const float4*)(Agk + (size_t)(aRow + 32 * i) * K + aCol);
            #pragma unroll
            for (int i = 0; i < 4; i++)
                bReg[i] = *(const float4*)(Bgk + (size_t)(bRow + 8 * i) * N + bCol);
        }

        const float* Ab = As + cur * A_BUF;
        const float* Bb = Bs + cur * B_BUF;
        #pragma unroll
        for (int kk = 0; kk < 32; kk += 8) {
            uint32_t af[4][4];
            uint32_t bf[4][2];
            #pragma unroll
            for (int mi = 0; mi < 4; mi++) {
                const float* p = Ab + (wm + mi * 16 + (lane >> 2)) * A_STRIDE + kk + (lane & 3);
                af[mi][0] = __float_as_uint(p[0]);
                af[mi][1] = __float_as_uint(p[8 * A_STRIDE]);
                af[mi][2] = __float_as_uint(p[4]);
                af[mi][3] = __float_as_uint(p[8 * A_STRIDE + 4]);
            }
            #pragma unroll
            for (int nj = 0; nj < 4; nj++) {
                const float* p = Bb + (kk + (lane & 3)) * B_STRIDE + wn + nj * 8 + (lane >> 2);
                bf[nj][0] = __float_as_uint(p[0]);
                bf[nj][1] = __float_as_uint(p[4 * B_STRIDE]);
            }
            #pragma unroll
            for (int mi = 0; mi < 4; mi++)
                #pragma unroll
                for (int nj = 0; nj < 4; nj++)
                    mma_tf32(acc[mi][nj], af[mi][0], af[mi][1], af[mi][2], af[mi][3],
                             bf[nj][0], bf[nj][1]);
        }

        if (kt + 1 < ntiles) {
            __syncthreads();
            float* Ao = As + (cur ^ 1) * A_BUF;
            float* Bo = Bs + (cur ^ 1) * B_BUF;
            #pragma unroll
            for (int i = 0; i < 4; i++) {
                float* p = Ao + (aRow + 32 * i) * A_STRIDE + aCol;
                p[0] = to_tf32(aReg[i].x); p[1] = to_tf32(aReg[i].y);
                p[2] = to_tf32(aReg[i].z); p[3] = to_tf32(aReg[i].w);
            }
            #pragma unroll
            for (int i = 0; i < 4; i++) {
                float* p = Bo + (bRow + 8 * i) * B_STRIDE + bCol;
                p[0] = to_tf32(bReg[i].x); p[1] = to_tf32(bReg[i].y);
                p[2] = to_tf32(bReg[i].z); p[3] = to_tf32(bReg[i].w);
            }
            __syncthreads();
            cur ^= 1;
        }
    }

    const int row0 = bm * 128 + wm + (lane >> 2);
    const int col0 = bn * 128 + wn + 2 * (lane & 3);
    #pragma unroll
    for (int mi = 0; mi < 4; mi++) {
        #pragma unroll
        for (int nj = 0; nj < 4; nj++) {
            int c = col0 + nj * 8;
            float2 bv = *(const float2*)(bias + c);
            #pragma unroll
            for (int half = 0; half < 2; half++) {
                int r = row0 + mi * 16 + half * 8;
                float* cp = C + (size_t)r * N + c;
                float v0 = acc[mi][nj][half * 2 + 0] + bv.x;
                float v1 = acc[mi][nj][half * 2 + 1] + bv.y;
                if (EPI == 1) { float2 rv = *(const float2*)cp; v0 += rv.x; v1 += rv.y; }
                if (EPI == 2) {
                    v0 = 0.5f * v0 * (1.0f + erff(v0 * 0.70710678118654752f));
                    v1 = 0.5f * v1 * (1.0f + erff(v1 * 0.70710678118654752f));
                }
                float2 w; w.x = v0; w.y = v1;
                *(float2*)cp = w;
            }
        }
    }
}

// ------------------------- flash attention (online softmax) ------------------
// One block per (q-tile 64, head, batch). t is Q=K=V.
// Streams 8 K/V tiles of 64; never materializes the 64x512 score matrix.
// smem ~72KB -> 3 CTAs/SM.
#define TSTRIDE 68
#define AQ 0
#define AK (64 * TSTRIDE)
#define AV (2 * 64 * TSTRIDE)
#define AP (3 * 64 * TSTRIDE)
#define ARS (4 * 64 * TSTRIDE)
#define ABIAS (ARS + 64)
#define ATT_SMEM_FLOATS (ABIAS + 512)

__global__ __launch_bounds__(256)
void attn_kernel(const float* __restrict__ t, const int* __restrict__ masked,
                 float* __restrict__ o) {
    extern __shared__ float sm[];
    float* QsT   = sm + AQ;     // [d][q] stride 68
    float* KsT   = sm + AK;     // [d][k] stride 68
    float* Vs    = sm + AV;     // [k][d] stride 68
    float* P     = sm + AP;     // [q][k] stride 68
    float* rs    = sm + ARS;    // per-row rescale / final 1/l
    float* biasS = sm + ABIAS;  // [512]

    const int qt = blockIdx.x, h = blockIdx.y, b = blockIdx.z;
    const int tid = threadIdx.x;

    for (int i = tid; i < 512; i += 256)
        biasS[i] = (masked[b * 512 + i] == 1) ? -1e9f : 0.0f;

    const int row = tid >> 2;
    const int d0  = (tid & 3) * 16;

    // Q tile -> QsT (transposed)
    {
        const float* qp = t + ((size_t)(b * 512 + qt * 64 + row)) * DD + h * 64 + d0;
        #pragma unroll
        for (int i = 0; i < 16; i += 4) {
            float4 v = *(const float4*)(qp + i);
            QsT[(d0 + i + 0) * TSTRIDE + row] = v.x;
            QsT[(d0 + i + 1) * TSTRIDE + row] = v.y;
            QsT[(d0 + i + 2) * TSTRIDE + row] = v.z;
            QsT[(d0 + i + 3) * TSTRIDE + row] = v.w;
        }
    }

    const float scale = 0.125f;
    const int aty = tid >> 4, atx = tid & 15;   // score-phase mapping
    const int rp  = tid >> 3, c0 = (tid & 7) * 8; // PV-phase mapping

    float m[4], l[4];
    #pragma unroll
    for (int i = 0; i < 4; i++) { m[i] = -1e30f; l[i] = 0.f; }
    float o0[8], o1[8];
    #pragma unroll
    for (int j = 0; j < 8; j++) { o0[j] = 0.f; o1[j] = 0.f; }

    for (int kt = 0; kt < 8; kt++) {
        // load K/V tile (same data, two layouts)
        const float* kp = t + ((size_t)(b * 512 + kt * 64 + row)) * DD + h * 64 + d0;
        float4 r0 = *(const float4*)(kp + 0);
        float4 r1 = *(const float4*)(kp + 4);
        float4 r2 = *(const float4*)(kp + 8);
        float4 r3 = *(const float4*)(kp + 12);
        __syncthreads();   // previous PV done (iter 0: no-op protection)
        KsT[(d0 + 0)  * TSTRIDE + row] = r0.x;
        KsT[(d0 + 1)  * TSTRIDE + row] = r0.y;
        KsT[(d0 + 2)  * TSTRIDE + row] = r0.z;
        KsT[(d0 + 3)  * TSTRIDE + row] = r0.w;
        KsT[(d0 + 4)  * TSTRIDE + row] = r1.x;
        KsT[(d0 + 5)  * TSTRIDE + row] = r1.y;
        KsT[(d0 + 6)  * TSTRIDE + row] = r1.z;
        KsT[(d0 + 7)  * TSTRIDE + row] = r1.w;
        KsT[(d0 + 8)  * TSTRIDE + row] = r2.x;
        KsT[(d0 + 9)  * TSTRIDE + row] = r2.y;
        KsT[(d0 + 10) * TSTRIDE + row] = r2.z;
        KsT[(d0 + 11) * TSTRIDE + row] = r2.w;
        KsT[(d0 + 12) * TSTRIDE + row] = r3.x;
        KsT[(d0 + 13) * TSTRIDE + row] = r3.y;
        KsT[(d0 + 14) * TSTRIDE + row] = r3.z;
        KsT[(d0 + 15) * TSTRIDE + row] = r3.w;
        *(float4*)&Vs[row * TSTRIDE + d0 + 0]  = r0;
        *(float4*)&Vs[row * TSTRIDE + d0 + 4]  = r1;
        *(float4*)&Vs[row * TSTRIDE + d0 + 8]  = r2;
        *(float4*)&Vs[row * TSTRIDE + d0 + 12] = r3;
        __syncthreads();   // tile (and on iter 0, Q/bias) ready

        // scores: S[4x4] for rows aty*4+i, keys atx*4+j
        float acc[4][4];
        #pragma unroll
        for (int i = 0; i < 4; i++)
            #pragma unroll
            for (int j = 0; j < 4; j++) acc[i][j] = 0.f;
        #pragma unroll 4
        for (int d = 0; d < 64; d++) {
            float4 qa = *(const float4*)&QsT[d * TSTRIDE + aty * 4];
            float4 ka = *(const float4*)&KsT[d * TSTRIDE + atx * 4];
            float qv[4] = {qa.x, qa.y, qa.z, qa.w};
            float kv[4] = {ka.x, ka.y, ka.z, ka.w};
            #pragma unroll
            for (int i = 0; i < 4; i++)
                #pragma unroll
                for (int j = 0; j < 4; j++)
                    acc[i][j] += qv[i] * kv[j];
        }

        // bias + online softmax update
        float bj[4];
        #pragma unroll
        for (int j = 0; j < 4; j++) bj[j] = biasS[kt * 64 + atx * 4 + j];

        #pragma unroll
        for (int i = 0; i < 4; i++) {
            float s0 = acc[i][0] * scale + bj[0];
            float s1 = acc[i][1] * scale + bj[1];
            float s2 = acc[i][2] * scale + bj[2];
            float s3 = acc[i][3] * scale + bj[3];
            acc[i][0] = s0; acc[i][1] = s1; acc[i][2] = s2; acc[i][3] = s3;
            float tm = fmaxf(fmaxf(s0, s1), fmaxf(s2, s3));
            tm = fmaxf(tm, __shfl_xor_sync(0xffffffffu, tm, 1));
            tm = fmaxf(tm, __shfl_xor_sync(0xffffffffu, tm, 2));
            tm = fmaxf(tm, __shfl_xor_sync(0xffffffffu, tm, 4));
            tm = fmaxf(tm, __shfl_xor_sync(0xffffffffu, tm, 8));
            float mn = fmaxf(m[i], tm);
            float sc = __expf(m[i] - mn);
            float p0 = __expf(s0 - mn);
            float p1 = __expf(s1 - mn);
            float p2 = __expf(s2 - mn);
            float p3 = __expf(s3 - mn);
            int r = aty * 4 + i;
            float4 pv; pv.x = p0; pv.y = p1; pv.z = p2; pv.w = p3;
            *(float4*)&P[r * TSTRIDE + atx * 4] = pv;
            float ps = p0 + p1 + p2 + p3;
            ps += __shfl_xor_sync(0xffffffffu, ps, 1);
            ps += __shfl_xor_sync(0xffffffffu, ps, 2);
            ps += __shfl_xor_sync(0xffffffffu, ps, 4);
            ps += __shfl_xor_sync(0xffffffffu, ps, 8);
            l[i] = l[i] * sc + ps;
            m[i] = mn;
            if (atx == 0) rs[r] = sc;
        }
        __syncthreads();   // P + rescale ready

        // PV: rows rp, rp+32, cols c0..c0+7
        float s0 = rs[rp], s1 = rs[rp + 32];
        #pragma unroll
        for (int j = 0; j < 8; j++) { o0[j] *= s0; o1[j] *= s1; }
        const float* pr0 = P + rp * TSTRIDE;
        const float* pr1 = P + (rp + 32) * TSTRIDE;
        #pragma unroll 4
        for (int k = 0; k < 64; k++) {
            float w0 = pr0[k];
            float w1 = pr1[k];
            float4 v0 = *(const float4*)&Vs[k * TSTRIDE + c0];
            float4 v1 = *(const float4*)&Vs[k * TSTRIDE + c0 + 4];
            o0[0] += w0 * v0.x; o0[1] += w0 * v0.y;
            o0[2] += w0 * v0.z; o0[3] += w0 * v0.w;
            o0[4] += w0 * v1.x; o0[5] += w0 * v1.y;
            o0[6] += w0 * v1.z; o0[7] += w0 * v1.w;
            o1[0] += w1 * v0.x; o1[1] += w1 * v0.y;
            o1[2] += w1 * v0.z; o1[3] += w1 * v0.w;
            o1[4] += w1 * v1.x; o1[5] += w1 * v1.y;
            o1[6] += w1 * v1.z; o1[7] += w1 * v1.w;
        }
    }

    __syncthreads();
    if (atx == 0) {
        #pragma unroll
        for (int i = 0; i < 4; i++) rs[aty * 4 + i] = 1.0f / l[i];
    }
    __syncthreads();

    float li0 = rs[rp], li1 = rs[rp + 32];
    float* op0 = o + ((size_t)(b * 512 + qt * 64 + rp)) * DD + h * 64 + c0;
    float* op1 = o + ((size_t)(b * 512 + qt * 64 + rp + 32)) * DD + h * 64 + c0;
    float4 w;
    w.x = o0[0] * li0; w.y = o0[1] * li0; w.z = o0[2] * li0; w.w = o0[3] * li0;
    *(float4*)(op0 + 0) = w;
    w.x = o0[4] * li0; w.y = o0[5] * li0; w.z = o0[6] * li0; w.w = o0[7] * li0;
    *(float4*)(op0 + 4) = w;
    w.x = o1[0] * li1; w.y = o1[1] * li1; w.z = o1[2] * li1; w.w = o1[3] * li1;
    *(float4*)(op1 + 0) = w;
    w.x = o1[4] * li1; w.y = o1[5] * li1; w.z = o1[6] * li1; w.w = o1[7] * li1;
    *(float4*)(op1 + 4) = w;
}

// ------------------------- host orchestration --------------------------------
extern "C" void kernel_launch(void* const* d_in, const int* in_sizes, int n_in,
                              void* d_out, int out_size) {
    const int*   masked = (const int*)  d_in[0];
    const float* tok    = (const float*)d_in[1];
    const float* seg    = (const float*)d_in[2];
    const float* ln1s   = (const float*)d_in[3];
    const float* ln1b   = (const float*)d_in[4];
    const float* wq     = (const float*)d_in[5];
    const float* bq     = (const float*)d_in[6];
    const float* wo     = (const float*)d_in[7];
    const float* bo     = (const float*)d_in[8];
    const float* ln2s   = (const float*)d_in[9];
    const float* ln2b   = (const float*)d_in[10];
    const float* w1     = (const float*)d_in[11];
    const float* b1     = (const float*)d_in[12];
    const float* w2     = (const float*)d_in[13];
    const float* b2     = (const float*)d_in[14];
    float* x = (float*)d_out;

    float *xn, *tt, *oo, *hh;
    cudaGetSymbolAddress((void**)&xn, g_xn);
    cudaGetSymbolAddress((void**)&tt, g_t);
    cudaGetSymbolAddress((void**)&oo, g_o);
    cudaGetSymbolAddress((void**)&hh, g_h);

    const size_t ATT_SMEM  = ATT_SMEM_FLOATS * sizeof(float);
    const size_t GEMM_SMEM = GEMM_SMEM_FLOATS * sizeof(float);
    cudaFuncSetAttribute(attn_kernel, cudaFuncAttributeMaxDynamicSharedMemorySize,
                         (int)ATT_SMEM);
    cudaFuncSetAttribute(gemm_tf32_kernel<0>, cudaFuncAttributeMaxDynamicSharedMemorySize,
                         (int)GEMM_SMEM);
    cudaFuncSetAttribute(gemm_tf32_kernel<1>, cudaFuncAttributeMaxDynamicSharedMemorySize,
                         (int)GEMM_SMEM);
    cudaFuncSetAttribute(gemm_tf32_kernel<2>, cudaFuncAttributeMaxDynamicSharedMemorySize,
                         (int)GEMM_SMEM);

    embed_kernel<<<ROWS, 256>>>(masked, tok, seg, x);

    for (int l = 0; l < LL; l++) {
        const float* wql = wq + (size_t)l * DD * DD;
        const float* wol = wo + (size_t)l * DD * DD;
        const float* w1l = w1 + (size_t)l * DD * DFFN;
        const float* w2l = w2 + (size_t)l * DFFN * DD;

        ln_kernel<<<ROWS, 256>>>(x, ln1s + l * DD, ln1b + l * DD, xn);
        gemm_tf32_kernel<0><<<dim3(DD / 128, ROWS / 128), 256, GEMM_SMEM>>>(
            xn, wql, bq + l * DD, tt, ROWS, DD, DD);
        attn_kernel<<<dim3(8, HH, BB), 256, ATT_SMEM>>>(tt, masked, oo);
        gemm_tf32_kernel<1><<<dim3(DD / 128, ROWS / 128), 256, GEMM_SMEM>>>(
            oo, wol, bo + l * DD, x, ROWS, DD, DD);
        ln_kernel<<<ROWS, 256>>>(x, ln2s + l * DD, ln2b + l * DD, xn);
        gemm_tf32_kernel<2><<<dim3(DFFN / 128, ROWS / 128), 256, GEMM_SMEM>>>(
            xn, w1l, b1 + l * DFFN, hh, ROWS, DFFN, DD);
        gemm_tf32_kernel<1><<<dim3(DD / 128, ROWS / 128), 256, GEMM_SMEM>>>(
            hh, w2l, b2 + l * DD, x, ROWS, DD, DFFN);
    }
}

// round 8
// speedup vs baseline: 2.6649x; 1.3109x over previous
#include <cuda_runtime.h>
#include <math.h>
#include <stdint.h>

#define BB 16
#define SS_ 512
#define DD 1024
#define HH 16
#define LL 12
#define DKK 64
#define DFFN 4096
#define ROWS (BB*SS_)   // 8192

// ------------------------- scratch (static device memory) -------------------
__device__ float g_xn[ROWS * DD];     // LN output
__device__ float g_t [ROWS * DD];     // shared QKV projection t
__device__ float g_o [ROWS * DD];     // attention output
__device__ float g_h [ROWS * DFFN];   // FFN hidden

__device__ __forceinline__ float to_tf32(float x) {
    uint32_t o;
    asm("cvt.rna.tf32.f32 %0, %1;" : "=r"(o) : "f"(x));
    return __uint_as_float(o);
}

__device__ __forceinline__ void mma_tf32(float c[4],
                                         uint32_t a0, uint32_t a1, uint32_t a2, uint32_t a3,
                                         uint32_t b0, uint32_t b1) {
    asm volatile(
        "mma.sync.aligned.m16n8k8.row.col.f32.tf32.tf32.f32 "
        "{%0,%1,%2,%3},{%4,%5,%6,%7},{%8,%9},{%0,%1,%2,%3};"
        : "+f"(c[0]), "+f"(c[1]), "+f"(c[2]), "+f"(c[3])
        : "r"(a0), "r"(a1), "r"(a2), "r"(a3), "r"(b0), "r"(b1));
}

// ------------------------- embedding + positional encoding ------------------
__global__ void embed_kernel(const int* __restrict__ masked,
                             const float* __restrict__ tok,
                             const float* __restrict__ seg,
                             float* __restrict__ x) {
    int bs = blockIdx.x;
    int s  = bs & (SS_ - 1);
    int id = masked[bs];
    const float* tp = tok + (size_t)id * DD;
    const float* sp = seg + DD;          // seg_emb[1]
    int j = threadIdx.x * 4;
    const float L = 0.0089944730328f;    // ln(10000)/1024
    float f0 = expf(-(float)j * L);
    float f1 = expf(-(float)(j + 2) * L);
    float a0 = (float)s * f0;
    float a1 = (float)s * f1;
    float4 tv = *(const float4*)(tp + j);
    float4 sv = *(const float4*)(sp + j);
    float4 r;
    r.x = tv.x + sinf(a0) + sv.x;
    r.y = tv.y + cosf(a0) + sv.y;
    r.z = tv.z + sinf(a1) + sv.z;
    r.w = tv.w + cosf(a1) + sv.w;
    *(float4*)(x + (size_t)bs * DD + j) = r;
}

// ------------------------- layernorm ---------------------------------------
__global__ void ln_kernel(const float* __restrict__ x,
                          const float* __restrict__ gamma,
                          const float* __restrict__ beta,
                          float* __restrict__ y) {
    int row = blockIdx.x;
    int tid = threadIdx.x;               // 256
    const float4* xp = (const float4*)(x + (size_t)row * DD);
    float4 v = xp[tid];
    float s = v.x + v.y + v.z + v.w;
    float q = v.x*v.x + v.y*v.y + v.z*v.z + v.w*v.w;
    #pragma unroll
    for (int o = 16; o > 0; o >>= 1) {
        s += __shfl_down_sync(0xffffffffu, s, o);
        q += __shfl_down_sync(0xffffffffu, q, o);
    }
    __shared__ float ss[8], qs[8];
    __shared__ float mu, rstd;
    int wid = tid >> 5, lane = tid & 31;
    if (lane == 0) { ss[wid] = s; qs[wid] = q; }
    __syncthreads();
    if (tid == 0) {
        float S = 0.f, Q = 0.f;
        #pragma unroll
        for (int i = 0; i < 8; i++) { S += ss[i]; Q += qs[i]; }
        float m = S * (1.0f / DD);
        mu = m;
        rstd = rsqrtf(Q * (1.0f / DD) - m * m + 1e-5f);
    }
    __syncthreads();
    int j = tid * 4;
    float4 g  = *(const float4*)(gamma + j);
    float4 bt = *(const float4*)(beta + j);
    float m = mu, r = rstd;
    float4 out;
    out.x = (v.x - m) * r * g.x + bt.x;
    out.y = (v.y - m) * r * g.y + bt.y;
    out.z = (v.z - m) * r * g.z + bt.z;
    out.w = (v.w - m) * r * g.w + bt.w;
    *(float4*)(y + (size_t)row * DD + j) = out;
}

// ------------------------- TF32 tensor-core GEMM -----------------------------
#define A_STRIDE 36    // [m][k] padded
#define B_STRIDE 132   // [k][n] padded
#define A_BUF (128 * A_STRIDE)
#define B_BUF (32 * B_STRIDE)
#define GEMM_SMEM_FLOATS (2 * A_BUF + 2 * B_BUF)

template <int EPI>
__global__ __launch_bounds__(256)
void gemm_tf32_kernel(const float* __restrict__ A, const float* __restrict__ B,
                      const float* __restrict__ bias, float* __restrict__ C,
                      int M, int N, int K) {
    extern __shared__ float sm[];
    float* As = sm;                 // [2][128][A_STRIDE]
    float* Bs = sm + 2 * A_BUF;     // [2][32][B_STRIDE]

    const int tid  = threadIdx.x;
    const int lane = tid & 31;
    const int warp = tid >> 5;
    const int wm = (warp & 1) * 64;
    const int wn = (warp >> 1) * 32;
    const int bm = blockIdx.y, bn = blockIdx.x;

    const int aRow = tid >> 3;
    const int aCol = (tid & 7) * 4;
    const int bRow = tid >> 5;
    const int bCol = (tid & 31) * 4;
    const float* Ag = A + (size_t)(bm * 128) * K;
    const float* Bg = B + bn * 128;

    float4 aReg[4], bReg[4];
    float acc[4][4][4];
    #pragma unroll
    for (int i = 0; i < 4; i++)
        #pragma unroll
        for (int j = 0; j < 4; j++)
            #pragma unroll
            for (int r = 0; r < 4; r++) acc[i][j][r] = 0.f;

    const int ntiles = K >> 5;

    #pragma unroll
    for (int i = 0; i < 4; i++)
        aReg[i] = *(const float4*)(Ag + (size_t)(aRow + 32 * i) * K + aCol);
    #pragma unroll
    for (int i = 0; i < 4; i++)
        bReg[i] = *(const float4*)(Bg + (size_t)(bRow + 8 * i) * N + bCol);
    #pragma unroll
    for (int i = 0; i < 4; i++) {
        float* p = As + (aRow + 32 * i) * A_STRIDE + aCol;
        p[0] = to_tf32(aReg[i].x); p[1] = to_tf32(aReg[i].y);
        p[2] = to_tf32(aReg[i].z); p[3] = to_tf32(aReg[i].w);
    }
    #pragma unroll
    for (int i = 0; i < 4; i++) {
        float* p = Bs + (bRow + 8 * i) * B_STRIDE + bCol;
        p[0] = to_tf32(bReg[i].x); p[1] = to_tf32(bReg[i].y);
        p[2] = to_tf32(bReg[i].z); p[3] = to_tf32(bReg[i].w);
    }
    __syncthreads();

    int cur = 0;
    for (int kt = 0; kt < ntiles; kt++) {
        if (kt + 1 < ntiles) {
            const float* Agk = Ag + (kt + 1) * 32;
            const float* Bgk = Bg + (size_t)((kt + 1) * 32) * N;
            #pragma unroll
            for (int i = 0; i < 4; i++)
                aReg[i] = *(const float4*)(Agk + (size_t)(aRow + 32 * i) * K + aCol);
            #pragma unroll
            for (int i = 0; i < 4; i++)
                bReg[i] = *(const float4*)(Bgk + (size_t)(bRow + 8 * i) * N + bCol);
        }

        const float* Ab = As + cur * A_BUF;
        const float* Bb = Bs + cur * B_BUF;
        #pragma unroll
        for (int kk = 0; kk < 32; kk += 8) {
            uint32_t af[4][4];
            uint32_t bf[4][2];
            #pragma unroll
            for (int mi = 0; mi < 4; mi++) {
                const float* p = Ab + (wm + mi * 16 + (lane >> 2)) * A_STRIDE + kk + (lane & 3);
                af[mi][0] = __float_as_uint(p[0]);
                af[mi][1] = __float_as_uint(p[8 * A_STRIDE]);
                af[mi][2] = __float_as_uint(p[4]);
                af[mi][3] = __float_as_uint(p[8 * A_STRIDE + 4]);
            }
            #pragma unroll
            for (int nj = 0; nj < 4; nj++) {
                const float* p = Bb + (kk + (lane & 3)) * B_STRIDE + wn + nj * 8 + (lane >> 2);
                bf[nj][0] = __float_as_uint(p[0]);
                bf[nj][1] = __float_as_uint(p[4 * B_STRIDE]);
            }
            #pragma unroll
            for (int mi = 0; mi < 4; mi++)
                #pragma unroll
                for (int nj = 0; nj < 4; nj++)
                    mma_tf32(acc[mi][nj], af[mi][0], af[mi][1], af[mi][2], af[mi][3],
                             bf[nj][0], bf[nj][1]);
        }

        if (kt + 1 < ntiles) {
            __syncthreads();
            float* Ao = As + (cur ^ 1) * A_BUF;
            float* Bo = Bs + (cur ^ 1) * B_BUF;
            #pragma unroll
            for (int i = 0; i < 4; i++) {
                float* p = Ao + (aRow + 32 * i) * A_STRIDE + aCol;
                p[0] = to_tf32(aReg[i].x); p[1] = to_tf32(aReg[i].y);
                p[2] = to_tf32(aReg[i].z); p[3] = to_tf32(aReg[i].w);
            }
            #pragma unroll
            for (int i = 0; i < 4; i++) {
                float* p = Bo + (bRow + 8 * i) * B_STRIDE + bCol;
                p[0] = to_tf32(bReg[i].x); p[1] = to_tf32(bReg[i].y);
                p[2] = to_tf32(bReg[i].z); p[3] = to_tf32(bReg[i].w);
            }
            __syncthreads();
            cur ^= 1;
        }
    }

    const int row0 = bm * 128 + wm + (lane >> 2);
    const int col0 = bn * 128 + wn + 2 * (lane & 3);
    #pragma unroll
    for (int mi = 0; mi < 4; mi++) {
        #pragma unroll
        for (int nj = 0; nj < 4; nj++) {
            int c = col0 + nj * 8;
            float2 bv = *(const float2*)(bias + c);
            #pragma unroll
            for (int half = 0; half < 2; half++) {
                int r = row0 + mi * 16 + half * 8;
                float* cp = C + (size_t)r * N + c;
                float v0 = acc[mi][nj][half * 2 + 0] + bv.x;
                float v1 = acc[mi][nj][half * 2 + 1] + bv.y;
                if (EPI == 1) { float2 rv = *(const float2*)cp; v0 += rv.x; v1 += rv.y; }
                if (EPI == 2) {
                    v0 = 0.5f * v0 * (1.0f + erff(v0 * 0.70710678118654752f));
                    v1 = 0.5f * v1 * (1.0f + erff(v1 * 0.70710678118654752f));
                }
                float2 w; w.x = v0; w.y = v1;
                *(float2*)cp = w;
            }
        }
    }
}

// ------------------------- tensor-core flash attention -----------------------
// CTA = 256 threads = 8 warps; 128 q-rows per CTA; grid (4, H, B).
// Each warp owns 16 q-rows. Streams 8 kv-tiles of 64 keys.
// Q, P in smem stride 76 (A-operand side); KV tile stride 72 (B-operand side).
// Online softmax stats are quad-local (each lane owns accumulator rows
// lane>>2 and lane>>2+8 of its warp's 16 rows).
#define ATQ_STRIDE 76
#define ATKV_STRIDE 72
#define AQ_OFF   0
#define AP_OFF   (128 * ATQ_STRIDE)
#define AKV_OFF  (2 * 128 * ATQ_STRIDE)
#define ABIAS_OFF (AKV_OFF + 64 * ATKV_STRIDE)
#define ATT_SMEM_FLOATS (ABIAS_OFF + 512)

__global__ __launch_bounds__(256)
void attn_kernel(const float* __restrict__ t, const int* __restrict__ masked,
                 float* __restrict__ o) {
    extern __shared__ float sm[];
    float* QS    = sm + AQ_OFF;    // [128][76]
    float* PS    = sm + AP_OFF;    // [128][76]
    float* KV    = sm + AKV_OFF;   // [64][72]  (keys row-major)
    float* biasS = sm + ABIAS_OFF; // [512]

    const int qt = blockIdx.x, h = blockIdx.y, b = blockIdx.z;
    const int tid = threadIdx.x;
    const int lane = tid & 31, w = tid >> 5;
    const int lq = lane >> 2, la = lane & 3;
    const int qr = w * 16;                 // warp's q-row base within tile

    for (int i = tid; i < 512; i += 256)
        biasS[i] = (masked[b * 512 + i] == 1) ? -1e9f : 0.0f;

    // load Q tile (128 x 64), tf32-rounded
    {
        int row = tid >> 1;
        int c0  = (tid & 1) * 32;
        const float* qp = t + ((size_t)(b * 512 + qt * 128 + row)) * DD + h * 64 + c0;
        float* qs = QS + row * ATQ_STRIDE + c0;
        #pragma unroll
        for (int i = 0; i < 32; i += 4) {
            float4 v = *(const float4*)(qp + i);
            qs[i + 0] = to_tf32(v.x); qs[i + 1] = to_tf32(v.y);
            qs[i + 2] = to_tf32(v.z); qs[i + 3] = to_tf32(v.w);
        }
    }

    const float scale = 0.125f;
    float m0 = -1e30f, m1 = -1e30f, l0 = 0.f, l1 = 0.f;
    float oacc[8][4];
    #pragma unroll
    for (int nf = 0; nf < 8; nf++)
        #pragma unroll
        for (int r = 0; r < 4; r++) oacc[nf][r] = 0.f;

    for (int kt = 0; kt < 8; kt++) {
        __syncthreads();  // prev PV done with KV; (kt=0: Q/bias stores done)
        // load KV tile (64 keys x 64 d), tf32-rounded
        {
            int row = tid >> 2;
            int c0  = (tid & 3) * 16;
            const float* kp = t + ((size_t)(b * 512 + kt * 64 + row)) * DD + h * 64 + c0;
            float* ks = KV + row * ATKV_STRIDE + c0;
            #pragma unroll
            for (int i = 0; i < 16; i += 4) {
                float4 v = *(const float4*)(kp + i);
                ks[i + 0] = to_tf32(v.x); ks[i + 1] = to_tf32(v.y);
                ks[i + 2] = to_tf32(v.z); ks[i + 3] = to_tf32(v.w);
            }
        }
        __syncthreads();

        // ---- phase A: S(16x64) = Q_w . K^T ----
        float s[8][4];
        #pragma unroll
        for (int nf = 0; nf < 8; nf++)
            #pragma unroll
            for (int r = 0; r < 4; r++) s[nf][r] = 0.f;

        #pragma unroll
        for (int kk = 0; kk < 8; kk++) {
            const float* ap = QS + (qr + lq) * ATQ_STRIDE + kk * 8 + la;
            uint32_t a0 = __float_as_uint(ap[0]);
            uint32_t a1 = __float_as_uint(ap[8 * ATQ_STRIDE]);
            uint32_t a2 = __float_as_uint(ap[4]);
            uint32_t a3 = __float_as_uint(ap[8 * ATQ_STRIDE + 4]);
            #pragma unroll
            for (int nf = 0; nf < 8; nf++) {
                const float* bp = KV + (nf * 8 + lq) * ATKV_STRIDE + kk * 8 + la;
                uint32_t b0 = __float_as_uint(bp[0]);
                uint32_t b1 = __float_as_uint(bp[4]);
                mma_tf32(s[nf], a0, a1, a2, a3, b0, b1);
            }
        }

        // ---- scale + bias + online softmax (quad-local) ----
        float tm0 = -1e30f, tm1 = -1e30f;
        #pragma unroll
        for (int nf = 0; nf < 8; nf++) {
            int c = kt * 64 + nf * 8 + 2 * la;
            float bv0 = biasS[c], bv1 = biasS[c + 1];
            s[nf][0] = s[nf][0] * scale + bv0;
            s[nf][1] = s[nf][1] * scale + bv1;
            s[nf][2] = s[nf][2] * scale + bv0;
            s[nf][3] = s[nf][3] * scale + bv1;
            tm0 = fmaxf(tm0, fmaxf(s[nf][0], s[nf][1]));
            tm1 = fmaxf(tm1, fmaxf(s[nf][2], s[nf][3]));
        }
        tm0 = fmaxf(tm0, __shfl_xor_sync(0xffffffffu, tm0, 1));
        tm0 = fmaxf(tm0, __shfl_xor_sync(0xffffffffu, tm0, 2));
        tm1 = fmaxf(tm1, __shfl_xor_sync(0xffffffffu, tm1, 1));
        tm1 = fmaxf(tm1, __shfl_xor_sync(0xffffffffu, tm1, 2));
        float mn0 = fmaxf(m0, tm0), mn1 = fmaxf(m1, tm1);
        float sc0 = __expf(m0 - mn0), sc1 = __expf(m1 - mn1);
        float ps0 = 0.f, ps1 = 0.f;
        float* pr0 = PS + (qr + lq) * ATQ_STRIDE + 2 * la;
        float* pr1 = PS + (qr + lq + 8) * ATQ_STRIDE + 2 * la;
        #pragma unroll
        for (int nf = 0; nf < 8; nf++) {
            float p0 = __expf(s[nf][0] - mn0);
            float p1 = __expf(s[nf][1] - mn0);
            float p2 = __expf(s[nf][2] - mn1);
            float p3 = __expf(s[nf][3] - mn1);
            ps0 += p0 + p1;
            ps1 += p2 + p3;
            pr0[nf * 8 + 0] = to_tf32(p0);
            pr0[nf * 8 + 1] = to_tf32(p1);
            pr1[nf * 8 + 0] = to_tf32(p2);
            pr1[nf * 8 + 1] = to_tf32(p3);
        }
        ps0 += __shfl_xor_sync(0xffffffffu, ps0, 1);
        ps0 += __shfl_xor_sync(0xffffffffu, ps0, 2);
        ps1 += __shfl_xor_sync(0xffffffffu, ps1, 1);
        ps1 += __shfl_xor_sync(0xffffffffu, ps1, 2);
        l0 = l0 * sc0 + ps0;
        l1 = l1 * sc1 + ps1;
        m0 = mn0; m1 = mn1;

        // rescale O accumulators
        #pragma unroll
        for (int nf = 0; nf < 8; nf++) {
            oacc[nf][0] *= sc0; oacc[nf][1] *= sc0;
            oacc[nf][2] *= sc1; oacc[nf][3] *= sc1;
        }
        __syncwarp();  // P tile rows are warp-private; order writes before reads

        // ---- phase PV: O(16x64) += P_w . V ----
        #pragma unroll
        for (int kk = 0; kk < 8; kk++) {
            const float* ap = PS + (qr + lq) * ATQ_STRIDE + kk * 8 + la;
            uint32_t a0 = __float_as_uint(ap[0]);
            uint32_t a1 = __float_as_uint(ap[8 * ATQ_STRIDE]);
            uint32_t a2 = __float_as_uint(ap[4]);
            uint32_t a3 = __float_as_uint(ap[8 * ATQ_STRIDE + 4]);
            #pragma unroll
            for (int nf = 0; nf < 8; nf++) {
                const float* bp = KV + (kk * 8 + la) * ATKV_STRIDE + nf * 8 + lq;
                uint32_t b0 = __float_as_uint(bp[0]);
                uint32_t b1 = __float_as_uint(bp[4 * ATKV_STRIDE]);
                mma_tf32(oacc[nf], a0, a1, a2, a3, b0, b1);
            }
        }
    }

    // ---- final normalize + store ----
    float li0 = 1.0f / l0, li1 = 1.0f / l1;
    const size_t grow = (size_t)(b * 512 + qt * 128 + qr + lq);
    #pragma unroll
    for (int nf = 0; nf < 8; nf++) {
        int col = h * 64 + nf * 8 + 2 * la;
        float2 v0; v0.x = oacc[nf][0] * li0; v0.y = oacc[nf][1] * li0;
        float2 v1; v1.x = oacc[nf][2] * li1; v1.y = oacc[nf][3] * li1;
        *(float2*)(o + grow * DD + col) = v0;
        *(float2*)(o + (grow + 8) * DD + col) = v1;
    }
}

// ------------------------- host orchestration --------------------------------
extern "C" void kernel_launch(void* const* d_in, const int* in_sizes, int n_in,
                              void* d_out, int out_size) {
    const int*   masked = (const int*)  d_in[0];
    const float* tok    = (const float*)d_in[1];
    const float* seg    = (const float*)d_in[2];
    const float* ln1s   = (const float*)d_in[3];
    const float* ln1b   = (const float*)d_in[4];
    const float* wq     = (const float*)d_in[5];
    const float* bq     = (const float*)d_in[6];
    const float* wo     = (const float*)d_in[7];
    const float* bo     = (const float*)d_in[8];
    const float* ln2s   = (const float*)d_in[9];
    const float* ln2b   = (const float*)d_in[10];
    const float* w1     = (const float*)d_in[11];
    const float* b1     = (const float*)d_in[12];
    const float* w2     = (const float*)d_in[13];
    const float* b2     = (const float*)d_in[14];
    float* x = (float*)d_out;

    float *xn, *tt, *oo, *hh;
    cudaGetSymbolAddress((void**)&xn, g_xn);
    cudaGetSymbolAddress((void**)&tt, g_t);
    cudaGetSymbolAddress((void**)&oo, g_o);
    cudaGetSymbolAddress((void**)&hh, g_h);

    const size_t ATT_SMEM  = ATT_SMEM_FLOATS * sizeof(float);
    const size_t GEMM_SMEM = GEMM_SMEM_FLOATS * sizeof(float);
    cudaFuncSetAttribute(attn_kernel, cudaFuncAttributeMaxDynamicSharedMemorySize,
                         (int)ATT_SMEM);
    cudaFuncSetAttribute(gemm_tf32_kernel<0>, cudaFuncAttributeMaxDynamicSharedMemorySize,
                         (int)GEMM_SMEM);
    cudaFuncSetAttribute(gemm_tf32_kernel<1>, cudaFuncAttributeMaxDynamicSharedMemorySize,
                         (int)GEMM_SMEM);
    cudaFuncSetAttribute(gemm_tf32_kernel<2>, cudaFuncAttributeMaxDynamicSharedMemorySize,
                         (int)GEMM_SMEM);

    embed_kernel<<<ROWS, 256>>>(masked, tok, seg, x);

    for (int l = 0; l < LL; l++) {
        const float* wql = wq + (size_t)l * DD * DD;
        const float* wol = wo + (size_t)l * DD * DD;
        const float* w1l = w1 + (size_t)l * DD * DFFN;
        const float* w2l = w2 + (size_t)l * DFFN * DD;

        ln_kernel<<<ROWS, 256>>>(x, ln1s + l * DD, ln1b + l * DD, xn);
        gemm_tf32_kernel<0><<<dim3(DD / 128, ROWS / 128), 256, GEMM_SMEM>>>(
            xn, wql, bq + l * DD, tt, ROWS, DD, DD);
        attn_kernel<<<dim3(4, HH, BB), 256, ATT_SMEM>>>(tt, masked, oo);
        gemm_tf32_kernel<1><<<dim3(DD / 128, ROWS / 128), 256, GEMM_SMEM>>>(
            oo, wol, bo + l * DD, x, ROWS, DD, DD);
        ln_kernel<<<ROWS, 256>>>(x, ln2s + l * DD, ln2b + l * DD, xn);
        gemm_tf32_kernel<2><<<dim3(DFFN / 128, ROWS / 128), 256, GEMM_SMEM>>>(
            xn, w1l, b1 + l * DFFN, hh, ROWS, DFFN, DD);
        gemm_tf32_kernel<1><<<dim3(DD / 128, ROWS / 128), 256, GEMM_SMEM>>>(
            hh, w2l, b2 + l * DD, x, ROWS, DD, DFFN);
    }
}

// round 10
// speedup vs baseline: 3.4109x; 1.2800x over previous
#include <cuda_runtime.h>
#include <math.h>
#include <stdint.h>

#define BB 16
#define SS_ 512
#define DD 1024
#define HH 16
#define LL 12
#define DKK 64
#define DFFN 4096
#define ROWS (BB*SS_)   // 8192

// ------------------------- scratch (static device memory) -------------------
__device__ float g_xn[ROWS * DD];     // LN output
__device__ float g_t [ROWS * DD];     // shared QKV projection t
__device__ float g_o [ROWS * DD];     // attention output
__device__ float g_h [ROWS * DFFN];   // FFN hidden

__device__ __forceinline__ float to_tf32(float x) {
    uint32_t o;
    asm("cvt.rna.tf32.f32 %0, %1;" : "=r"(o) : "f"(x));
    return __uint_as_float(o);
}

__device__ __forceinline__ void mma_tf32(float c[4],
                                         uint32_t a0, uint32_t a1, uint32_t a2, uint32_t a3,
                                         uint32_t b0, uint32_t b1) {
    asm volatile(
        "mma.sync.aligned.m16n8k8.row.col.f32.tf32.tf32.f32 "
        "{%0,%1,%2,%3},{%4,%5,%6,%7},{%8,%9},{%0,%1,%2,%3};"
        : "+f"(c[0]), "+f"(c[1]), "+f"(c[2]), "+f"(c[3])
        : "r"(a0), "r"(a1), "r"(a2), "r"(a3), "r"(b0), "r"(b1));
}

// ------------------------- embedding + positional encoding ------------------
__global__ void embed_kernel(const int* __restrict__ masked,
                             const float* __restrict__ tok,
                             const float* __restrict__ seg,
                             float* __restrict__ x) {
    int bs = blockIdx.x;
    int s  = bs & (SS_ - 1);
    int id = masked[bs];
    const float* tp = tok + (size_t)id * DD;
    const float* sp = seg + DD;          // seg_emb[1]
    int j = threadIdx.x * 4;
    const float L = 0.0089944730328f;    // ln(10000)/1024
    float f0 = expf(-(float)j * L);
    float f1 = expf(-(float)(j + 2) * L);
    float a0 = (float)s * f0;
    float a1 = (float)s * f1;
    float4 tv = *(const float4*)(tp + j);
    float4 sv = *(const float4*)(sp + j);
    float4 r;
    r.x = tv.x + sinf(a0) + sv.x;
    r.y = tv.y + cosf(a0) + sv.y;
    r.z = tv.z + sinf(a1) + sv.z;
    r.w = tv.w + cosf(a1) + sv.w;
    *(float4*)(x + (size_t)bs * DD + j) = r;
}

// ------------------------- layernorm (warp-per-row, no block sync) ----------
__global__ void ln_kernel(const float* __restrict__ x,
                          const float* __restrict__ gamma,
                          const float* __restrict__ beta,
                          float* __restrict__ y) {
    const int row  = blockIdx.x * 8 + (threadIdx.x >> 5);
    const int lane = threadIdx.x & 31;
    const float4* xp = (const float4*)(x + (size_t)row * DD);
    float4 v[8];
    float s = 0.f, q = 0.f;
    #pragma unroll
    for (int i = 0; i < 8; i++) {
        v[i] = xp[lane + 32 * i];
        s += v[i].x + v[i].y + v[i].z + v[i].w;
        q += v[i].x * v[i].x + v[i].y * v[i].y + v[i].z * v[i].z + v[i].w * v[i].w;
    }
    #pragma unroll
    for (int o = 16; o > 0; o >>= 1) {
        s += __shfl_xor_sync(0xffffffffu, s, o);
        q += __shfl_xor_sync(0xffffffffu, q, o);
    }
    float m = s * (1.0f / DD);
    float r = rsqrtf(q * (1.0f / DD) - m * m + 1e-5f);
    const float4* gp = (const float4*)gamma;
    const float4* bp = (const float4*)beta;
    float4* yp = (float4*)(y + (size_t)row * DD);
    #pragma unroll
    for (int i = 0; i < 8; i++) {
        float4 g = gp[lane + 32 * i];
        float4 b = bp[lane + 32 * i];
        float4 o4;
        o4.x = (v[i].x - m) * r * g.x + b.x;
        o4.y = (v[i].y - m) * r * g.y + b.y;
        o4.z = (v[i].z - m) * r * g.z + b.z;
        o4.w = (v[i].w - m) * r * g.w + b.w;
        yp[lane + 32 * i] = o4;
    }
}

// ------------------------- TF32 tensor-core GEMM -----------------------------
// C[M,N] = A[M,K] * B[K,N]  (row-major), fp32 accum, tf32 inputs (rna-rounded).
// CTA tile 128x128, k-tile 32, 8 warps, warp tile 64x32 (4x4 m16n8k8 frags).
// Single-sync store-overlap double buffer; __launch_bounds__(256,2) for 2 CTA/SM.
// EPI: 0 = bias, 1 = bias + residual (C in-place), 2 = bias + exact GELU.
#define A_STRIDE 36    // [m][k] padded
#define B_STRIDE 132   // [k][n] padded
#define A_BUF (128 * A_STRIDE)
#define B_BUF (32 * B_STRIDE)
#define GEMM_SMEM_FLOATS (2 * A_BUF + 2 * B_BUF)

template <int EPI>
__global__ __launch_bounds__(256, 2)
void gemm_tf32_kernel(const float* __restrict__ A, const float* __restrict__ B,
                      const float* __restrict__ bias, float* __restrict__ C,
                      int M, int N, int K) {
    extern __shared__ float sm[];
    float* As = sm;                 // [2][128][A_STRIDE]
    float* Bs = sm + 2 * A_BUF;     // [2][32][B_STRIDE]

    const int tid  = threadIdx.x;
    const int lane = tid & 31;
    const int warp = tid >> 5;
    const int wm = (warp & 1) * 64;
    const int wn = (warp >> 1) * 32;
    const int bm = blockIdx.y, bn = blockIdx.x;

    const int aRow = tid >> 3;          // 0..31 (4 passes of 32 rows)
    const int aCol = (tid & 7) * 4;
    const int bRow = tid >> 5;          // 0..7 (4 passes of 8 rows)
    const int bCol = (tid & 31) * 4;
    const float* Ag = A + (size_t)(bm * 128) * K;
    const float* Bg = B + bn * 128;

    float4 aReg[4], bReg[4];
    float acc[4][4][4];
    #pragma unroll
    for (int i = 0; i < 4; i++)
        #pragma unroll
        for (int j = 0; j < 4; j++)
            #pragma unroll
            for (int r = 0; r < 4; r++) acc[i][j][r] = 0.f;

    const int ntiles = K >> 5;

    // ---- prologue: tile 0 -> smem buf0; tile 1 -> regs; sync ----
    #pragma unroll
    for (int i = 0; i < 4; i++)
        aReg[i] = *(const float4*)(Ag + (size_t)(aRow + 32 * i) * K + aCol);
    #pragma unroll
    for (int i = 0; i < 4; i++)
        bReg[i] = *(const float4*)(Bg + (size_t)(bRow + 8 * i) * N + bCol);
    #pragma unroll
    for (int i = 0; i < 4; i++) {
        float* p = As + (aRow + 32 * i) * A_STRIDE + aCol;
        p[0] = to_tf32(aReg[i].x); p[1] = to_tf32(aReg[i].y);
        p[2] = to_tf32(aReg[i].z); p[3] = to_tf32(aReg[i].w);
    }
    #pragma unroll
    for (int i = 0; i < 4; i++) {
        float* p = Bs + (bRow + 8 * i) * B_STRIDE + bCol;
        p[0] = to_tf32(bReg[i].x); p[1] = to_tf32(bReg[i].y);
        p[2] = to_tf32(bReg[i].z); p[3] = to_tf32(bReg[i].w);
    }
    if (ntiles > 1) {
        const float* Agk = Ag + 32;
        const float* Bgk = Bg + (size_t)32 * N;
        #pragma unroll
        for (int i = 0; i < 4; i++)
            aReg[i] = *(const float4*)(Agk + (size_t)(aRow + 32 * i) * K + aCol);
        #pragma unroll
        for (int i = 0; i < 4; i++)
            bReg[i] = *(const float4*)(Bgk + (size_t)(bRow + 8 * i) * N + bCol);
    }
    __syncthreads();

    for (int kt = 0; kt < ntiles; kt++) {
        const int buf = kt & 1;

        // store tile kt+1 (in regs) into the other buffer — overlaps with compute
        if (kt + 1 < ntiles) {
            float* Ao = As + (buf ^ 1) * A_BUF;
            float* Bo = Bs + (buf ^ 1) * B_BUF;
            #pragma unroll
            for (int i = 0; i < 4; i++) {
                float* p = Ao + (aRow + 32 * i) * A_STRIDE + aCol;
                p[0] = to_tf32(aReg[i].x); p[1] = to_tf32(aReg[i].y);
                p[2] = to_tf32(aReg[i].z); p[3] = to_tf32(aReg[i].w);
            }
            #pragma unroll
            for (int i = 0; i < 4; i++) {
                float* p = Bo + (bRow + 8 * i) * B_STRIDE + bCol;
                p[0] = to_tf32(bReg[i].x); p[1] = to_tf32(bReg[i].y);
                p[2] = to_tf32(bReg[i].z); p[3] = to_tf32(bReg[i].w);
            }
        }
        // kick off gmem loads for tile kt+2 (land during compute)
        if (kt + 2 < ntiles) {
            const float* Agk = Ag + (kt + 2) * 32;
            const float* Bgk = Bg + (size_t)((kt + 2) * 32) * N;
            #pragma unroll
            for (int i = 0; i < 4; i++)
                aReg[i] = *(const float4*)(Agk + (size_t)(aRow + 32 * i) * K + aCol);
            #pragma unroll
            for (int i = 0; i < 4; i++)
                bReg[i] = *(const float4*)(Bgk + (size_t)(bRow + 8 * i) * N + bCol);
        }

        // compute on current buffer
        const float* Ab = As + buf * A_BUF;
        const float* Bb = Bs + buf * B_BUF;
        #pragma unroll
        for (int kk = 0; kk < 32; kk += 8) {
            uint32_t af[4][4];
            uint32_t bf[4][2];
            #pragma unroll
            for (int mi = 0; mi < 4; mi++) {
                const float* p = Ab + (wm + mi * 16 + (lane >> 2)) * A_STRIDE + kk + (lane & 3);
                af[mi][0] = __float_as_uint(p[0]);
                af[mi][1] = __float_as_uint(p[8 * A_STRIDE]);
                af[mi][2] = __float_as_uint(p[4]);
                af[mi][3] = __float_as_uint(p[8 * A_STRIDE + 4]);
            }
            #pragma unroll
            for (int nj = 0; nj < 4; nj++) {
                const float* p = Bb + (kk + (lane & 3)) * B_STRIDE + wn + nj * 8 + (lane >> 2);
                bf[nj][0] = __float_as_uint(p[0]);
                bf[nj][1] = __float_as_uint(p[4 * B_STRIDE]);
            }
            #pragma unroll
            for (int mi = 0; mi < 4; mi++)
                #pragma unroll
                for (int nj = 0; nj < 4; nj++)
                    mma_tf32(acc[mi][nj], af[mi][0], af[mi][1], af[mi][2], af[mi][3],
                             bf[nj][0], bf[nj][1]);
        }

        if (kt + 1 < ntiles) __syncthreads();
    }

    // ---- epilogue ----
    const int row0 = bm * 128 + wm + (lane >> 2);
    const int col0 = bn * 128 + wn + 2 * (lane & 3);
    #pragma unroll
    for (int mi = 0; mi < 4; mi++) {
        #pragma unroll
        for (int nj = 0; nj < 4; nj++) {
            int c = col0 + nj * 8;
            float2 bv = *(const float2*)(bias + c);
            #pragma unroll
            for (int half = 0; half < 2; half++) {
                int r = row0 + mi * 16 + half * 8;
                float* cp = C + (size_t)r * N + c;
                float v0 = acc[mi][nj][half * 2 + 0] + bv.x;
                float v1 = acc[mi][nj][half * 2 + 1] + bv.y;
                if (EPI == 1) { float2 rv = *(const float2*)cp; v0 += rv.x; v1 += rv.y; }
                if (EPI == 2) {
                    v0 = 0.5f * v0 * (1.0f + erff(v0 * 0.70710678118654752f));
                    v1 = 0.5f * v1 * (1.0f + erff(v1 * 0.70710678118654752f));
                }
                float2 w; w.x = v0; w.y = v1;
                *(float2*)cp = w;
            }
        }
    }
}

// ------------------------- tensor-core flash attention -----------------------
#define ATQ_STRIDE 76
#define ATKV_STRIDE 72
#define AQ_OFF   0
#define AP_OFF   (128 * ATQ_STRIDE)
#define AKV_OFF  (2 * 128 * ATQ_STRIDE)
#define ABIAS_OFF (AKV_OFF + 64 * ATKV_STRIDE)
#define ATT_SMEM_FLOATS (ABIAS_OFF + 512)

__global__ __launch_bounds__(256)
void attn_kernel(const float* __restrict__ t, const int* __restrict__ masked,
                 float* __restrict__ o) {
    extern __shared__ float sm[];
    float* QS    = sm + AQ_OFF;    // [128][76]
    float* PS    = sm + AP_OFF;    // [128][76]
    float* KV    = sm + AKV_OFF;   // [64][72]  (keys row-major)
    float* biasS = sm + ABIAS_OFF; // [512]

    const int qt = blockIdx.x, h = blockIdx.y, b = blockIdx.z;
    const int tid = threadIdx.x;
    const int lane = tid & 31, w = tid >> 5;
    const int lq = lane >> 2, la = lane & 3;
    const int qr = w * 16;                 // warp's q-row base within tile

    for (int i = tid; i < 512; i += 256)
        biasS[i] = (masked[b * 512 + i] == 1) ? -1e9f : 0.0f;

    {
        int row = tid >> 1;
        int c0  = (tid & 1) * 32;
        const float* qp = t + ((size_t)(b * 512 + qt * 128 + row)) * DD + h * 64 + c0;
        float* qs = QS + row * ATQ_STRIDE + c0;
        #pragma unroll
        for (int i = 0; i < 32; i += 4) {
            float4 v = *(const float4*)(qp + i);
            qs[i + 0] = to_tf32(v.x); qs[i + 1] = to_tf32(v.y);
            qs[i + 2] = to_tf32(v.z); qs[i + 3] = to_tf32(v.w);
        }
    }

    const float scale = 0.125f;
    float m0 = -1e30f, m1 = -1e30f, l0 = 0.f, l1 = 0.f;
    float oacc[8][4];
    #pragma unroll
    for (int nf = 0; nf < 8; nf++)
        #pragma unroll
        for (int r = 0; r < 4; r++) oacc[nf][r] = 0.f;

    for (int kt = 0; kt < 8; kt++) {
        __syncthreads();
        {
            int row = tid >> 2;
            int c0  = (tid & 3) * 16;
            const float* kp = t + ((size_t)(b * 512 + kt * 64 + row)) * DD + h * 64 + c0;
            float* ks = KV + row * ATKV_STRIDE + c0;
            #pragma unroll
            for (int i = 0; i < 16; i += 4) {
                float4 v = *(const float4*)(kp + i);
                ks[i + 0] = to_tf32(v.x); ks[i + 1] = to_tf32(v.y);
                ks[i + 2] = to_tf32(v.z); ks[i + 3] = to_tf32(v.w);
            }
        }
        __syncthreads();

        float s[8][4];
        #pragma unroll
        for (int nf = 0; nf < 8; nf++)
            #pragma unroll
            for (int r = 0; r < 4; r++) s[nf][r] = 0.f;

        #pragma unroll
        for (int kk = 0; kk < 8; kk++) {
            const float* ap = QS + (qr + lq) * ATQ_STRIDE + kk * 8 + la;
            uint32_t a0 = __float_as_uint(ap[0]);
            uint32_t a1 = __float_as_uint(ap[8 * ATQ_STRIDE]);
            uint32_t a2 = __float_as_uint(ap[4]);
            uint32_t a3 = __float_as_uint(ap[8 * ATQ_STRIDE + 4]);
            #pragma unroll
            for (int nf = 0; nf < 8; nf++) {
                const float* bp = KV + (nf * 8 + lq) * ATKV_STRIDE + kk * 8 + la;
                uint32_t b0 = __float_as_uint(bp[0]);
                uint32_t b1 = __float_as_uint(bp[4]);
                mma_tf32(s[nf], a0, a1, a2, a3, b0, b1);
            }
        }

        float tm0 = -1e30f, tm1 = -1e30f;
        #pragma unroll
        for (int nf = 0; nf < 8; nf++) {
            int c = kt * 64 + nf * 8 + 2 * la;
            float bv0 = biasS[c], bv1 = biasS[c + 1];
            s[nf][0] = s[nf][0] * scale + bv0;
            s[nf][1] = s[nf][1] * scale + bv1;
            s[nf][2] = s[nf][2] * scale + bv0;
            s[nf][3] = s[nf][3] * scale + bv1;
            tm0 = fmaxf(tm0, fmaxf(s[nf][0], s[nf][1]));
            tm1 = fmaxf(tm1, fmaxf(s[nf][2], s[nf][3]));
        }
        tm0 = fmaxf(tm0, __shfl_xor_sync(0xffffffffu, tm0, 1));
        tm0 = fmaxf(tm0, __shfl_xor_sync(0xffffffffu, tm0, 2));
        tm1 = fmaxf(tm1, __shfl_xor_sync(0xffffffffu, tm1, 1));
        tm1 = fmaxf(tm1, __shfl_xor_sync(0xffffffffu, tm1, 2));
        float mn0 = fmaxf(m0, tm0), mn1 = fmaxf(m1, tm1);
        float sc0 = __expf(m0 - mn0), sc1 = __expf(m1 - mn1);
        float ps0 = 0.f, ps1 = 0.f;
        float* pr0 = PS + (qr + lq) * ATQ_STRIDE + 2 * la;
        float* pr1 = PS + (qr + lq + 8) * ATQ_STRIDE + 2 * la;
        #pragma unroll
        for (int nf = 0; nf < 8; nf++) {
            float p0 = __expf(s[nf][0] - mn0);
            float p1 = __expf(s[nf][1] - mn0);
            float p2 = __expf(s[nf][2] - mn1);
            float p3 = __expf(s[nf][3] - mn1);
            ps0 += p0 + p1;
            ps1 += p2 + p3;
            pr0[nf * 8 + 0] = to_tf32(p0);
            pr0[nf * 8 + 1] = to_tf32(p1);
            pr1[nf * 8 + 0] = to_tf32(p2);
            pr1[nf * 8 + 1] = to_tf32(p3);
        }
        ps0 += __shfl_xor_sync(0xffffffffu, ps0, 1);
        ps0 += __shfl_xor_sync(0xffffffffu, ps0, 2);
        ps1 += __shfl_xor_sync(0xffffffffu, ps1, 1);
        ps1 += __shfl_xor_sync(0xffffffffu, ps1, 2);
        l0 = l0 * sc0 + ps0;
        l1 = l1 * sc1 + ps1;
        m0 = mn0; m1 = mn1;

        #pragma unroll
        for (int nf = 0; nf < 8; nf++) {
            oacc[nf][0] *= sc0; oacc[nf][1] *= sc0;
            oacc[nf][2] *= sc1; oacc[nf][3] *= sc1;
        }
        __syncwarp();

        #pragma unroll
        for (int kk = 0; kk < 8; kk++) {
            const float* ap = PS + (qr + lq) * ATQ_STRIDE + kk * 8 + la;
            uint32_t a0 = __float_as_uint(ap[0]);
            uint32_t a1 = __float_as_uint(ap[8 * ATQ_STRIDE]);
            uint32_t a2 = __float_as_uint(ap[4]);
            uint32_t a3 = __float_as_uint(ap[8 * ATQ_STRIDE + 4]);
            #pragma unroll
            for (int nf = 0; nf < 8; nf++) {
                const float* bp = KV + (kk * 8 + la) * ATKV_STRIDE + nf * 8 + lq;
                uint32_t b0 = __float_as_uint(bp[0]);
                uint32_t b1 = __float_as_uint(bp[4 * ATKV_STRIDE]);
                mma_tf32(oacc[nf], a0, a1, a2, a3, b0, b1);
            }
        }
    }

    float li0 = 1.0f / l0, li1 = 1.0f / l1;
    const size_t grow = (size_t)(b * 512 + qt * 128 + qr + lq);
    #pragma unroll
    for (int nf = 0; nf < 8; nf++) {
        int col = h * 64 + nf * 8 + 2 * la;
        float2 v0; v0.x = oacc[nf][0] * li0; v0.y = oacc[nf][1] * li0;
        float2 v1; v1.x = oacc[nf][2] * li1; v1.y = oacc[nf][3] * li1;
        *(float2*)(o + grow * DD + col) = v0;
        *(float2*)(o + (grow + 8) * DD + col) = v1;
    }
}

// ------------------------- host orchestration --------------------------------
extern "C" void kernel_launch(void* const* d_in, const int* in_sizes, int n_in,
                              void* d_out, int out_size) {
    const int*   masked = (const int*)  d_in[0];
    const float* tok    = (const float*)d_in[1];
    const float* seg    = (const float*)d_in[2];
    const float* ln1s   = (const float*)d_in[3];
    const float* ln1b   = (const float*)d_in[4];
    const float* wq     = (const float*)d_in[5];
    const float* bq     = (const float*)d_in[6];
    const float* wo     = (const float*)d_in[7];
    const float* bo     = (const float*)d_in[8];
    const float* ln2s   = (const float*)d_in[9];
    const float* ln2b   = (const float*)d_in[10];
    const float* w1     = (const float*)d_in[11];
    const float* b1     = (const float*)d_in[12];
    const float* w2     = (const float*)d_in[13];
    const float* b2     = (const float*)d_in[14];
    float* x = (float*)d_out;

    float *xn, *tt, *oo, *hh;
    cudaGetSymbolAddress((void**)&xn, g_xn);
    cudaGetSymbolAddress((void**)&tt, g_t);
    cudaGetSymbolAddress((void**)&oo, g_o);
    cudaGetSymbolAddress((void**)&hh, g_h);

    const size_t ATT_SMEM  = ATT_SMEM_FLOATS * sizeof(float);
    const size_t GEMM_SMEM = GEMM_SMEM_FLOATS * sizeof(float);
    cudaFuncSetAttribute(attn_kernel, cudaFuncAttributeMaxDynamicSharedMemorySize,
                         (int)ATT_SMEM);
    cudaFuncSetAttribute(gemm_tf32_kernel<0>, cudaFuncAttributeMaxDynamicSharedMemorySize,
                         (int)GEMM_SMEM);
    cudaFuncSetAttribute(gemm_tf32_kernel<1>, cudaFuncAttributeMaxDynamicSharedMemorySize,
                         (int)GEMM_SMEM);
    cudaFuncSetAttribute(gemm_tf32_kernel<2>, cudaFuncAttributeMaxDynamicSharedMemorySize,
                         (int)GEMM_SMEM);

    embed_kernel<<<ROWS, 256>>>(masked, tok, seg, x);

    for (int l = 0; l < LL; l++) {
        const float* wql = wq + (size_t)l * DD * DD;
        const float* wol = wo + (size_t)l * DD * DD;
        const float* w1l = w1 + (size_t)l * DD * DFFN;
        const float* w2l = w2 + (size_t)l * DFFN * DD;

        ln_kernel<<<ROWS / 8, 256>>>(x, ln1s + l * DD, ln1b + l * DD, xn);
        gemm_tf32_kernel<0><<<dim3(DD / 128, ROWS / 128), 256, GEMM_SMEM>>>(
            xn, wql, bq + l * DD, tt, ROWS, DD, DD);
        attn_kernel<<<dim3(4, HH, BB), 256, ATT_SMEM>>>(tt, masked, oo);
        gemm_tf32_kernel<1><<<dim3(DD / 128, ROWS / 128), 256, GEMM_SMEM>>>(
            oo, wol, bo + l * DD, x, ROWS, DD, DD);
        ln_kernel<<<ROWS / 8, 256>>>(x, ln2s + l * DD, ln2b + l * DD, xn);
        gemm_tf32_kernel<2><<<dim3(DFFN / 128, ROWS / 128), 256, GEMM_SMEM>>>(
            xn, w1l, b1 + l * DFFN, hh, ROWS, DFFN, DD);
        gemm_tf32_kernel<1><<<dim3(DD / 128, ROWS / 128), 256, GEMM_SMEM>>>(
            hh, w2l, b2 + l * DD, x, ROWS, DD, DFFN);
    }
}